// round 11
// baseline (speedup 1.0000x reference)
#include <cuda_runtime.h>
#include <math.h>
#include <stdint.h>

typedef unsigned long long ull;

#define B 64
#define H 1024
#define HY 256
#define F 64
#define IND 133
#define NSEQ 128
#define OUTD 123
#define GRID 148

// ---------------- persistent device state ----------------------------------
__device__ __align__(16) float g_h[H][B];
__device__ __align__(16) float g_c[H][B];
__device__ __align__(16) float g_hh[2][HY][B];
__device__ __align__(16) float g_ch[HY][B];
__device__ __align__(16) float g_ahp[4][4 * H][B];      // h@Wh split-K partials
__device__ __align__(16) float g_x[NSEQ][IND][B];
__device__ __align__(16) float g_axp[NSEQ][4 * H][B];   // precomputed x@Wx
__device__ __align__(16) float g_gxh[NSEQ][4 * HY][B];  // precomputed x@Wxh(x-rows)
__device__ __align__(16) float g_E[3][HY][4 * H];       // fused Wz@D (12.6MB)
__device__ __align__(16) float g_Ebias[2][4 * H];       // bz@D (zb has no bias)
__device__ __align__(16) float g_outs[NSEQ][H][B];
__device__ __align__(16) float g_dec[NSEQ][OUTD][B];
__device__ volatile unsigned g_flag[GRID];              // barrier flags (epoch)

__device__ __forceinline__ float sigf(float x) { return 1.0f / (1.0f + expf(-x)); }

__device__ __forceinline__ void fma2(ull& d, ull a, ull b) {
    asm("fma.rn.f32x2 %0, %1, %2, %0;" : "+l"(d) : "l"(a), "l"(b));
}
__device__ __forceinline__ ull mul2(ull a, ull b) {
    ull d; asm("mul.rn.f32x2 %0, %1, %2;" : "=l"(d) : "l"(a), "l"(b)); return d;
}
__device__ __forceinline__ ull add2(ull a, ull b) {
    ull d; asm("add.rn.f32x2 %0, %1, %2;" : "=l"(d) : "l"(a), "l"(b)); return d;
}
__device__ __forceinline__ ull pack2(float x, float y) {
    ull r; asm("mov.b64 %0, {%1, %2};" : "=l"(r) : "f"(x), "f"(y)); return r;
}
__device__ __forceinline__ void unpack2(ull v, float& lo, float& hi) {
    asm("mov.b64 {%0, %1}, %2;" : "=f"(lo), "=f"(hi) : "l"(v));
}

// ---------------- cp.async helpers ------------------------------------------
__device__ __forceinline__ void cpa16(void* dst, const void* src) {
    unsigned d = (unsigned)__cvta_generic_to_shared(dst);
    asm volatile("cp.async.cg.shared.global [%0], [%1], 16;" :: "r"(d), "l"(src));
}
__device__ __forceinline__ void cpa_commit() {
    asm volatile("cp.async.commit_group;");
}
template<int N>
__device__ __forceinline__ void cpa_wait() {
    asm volatile("cp.async.wait_group %0;" :: "n"(N));
}

// ---------------- fast flag-array grid barrier ------------------------------
// Arrival: each block writes its epoch to its own flag. Detection: 148
// threads poll all flags in parallel. Acquire: one __threadfence (CCTL.IVALL)
// so post-barrier plain LDGs of cross-SM data (g_ahp) miss stale L1.
__device__ __forceinline__ void grid_bar(unsigned ep, int bx, int tid) {
    __syncthreads();
    if (tid == 0) {
        __threadfence();                       // release: my block's STGs -> L2
        g_flag[bx] = ep;
    }
    if (tid < GRID) {
        while (g_flag[tid] < ep) {}
    }
    __syncthreads();
    if (tid == 0) __threadfence();             // acquire: invalidate L1D
    __syncthreads();
}

// ---------------- col-pair GEMM building blocks ------------------------------
// Thread mapping: b = tid & 63 (one batch), cg8 = (tid>>6)*8 (8 cols).
// acc[i] = f32x2 over cols (cg8+2i, cg8+2i+1) for batch b.
__device__ __forceinline__ void stage_A(float* dA, const float* A, int k0, int tid) {
    int ar = tid >> 4, ac4 = (tid & 15) << 2;
    cpa16(dA + ar * 64 + ac4, A + (k0 + ar) * 64 + ac4);
    cpa16(dA + (ar + 16) * 64 + ac4, A + (k0 + ar + 16) * 64 + ac4);
}
// GS=0: contiguous cols cb..cb+31. GS>0: 4 groups of 8 cols, group g at
// W col g*GS + cb + (0..7).
template<int GS>
__device__ __forceinline__ void stage_W(float* dW, const float* W, int ldw,
                                        int cb, int k0, int tid) {
    int wr = tid >> 3, wq = tid & 7;
    const float* ws = GS ? (W + (k0 + wr) * ldw + (wq >> 1) * GS + cb + ((wq & 1) << 2))
                         : (W + (k0 + wr) * ldw + cb + (wq << 2));
    cpa16(dW + wr * 32 + (wq << 2), ws);
}

__device__ __forceinline__ void cp_compute(const float* cA, const float* cW,
                                           int b, int cg8, ull (&acc)[4]) {
#pragma unroll
    for (int k = 0; k < 32; k++) {
        float av = cA[k * 64 + b];
        ull a2 = pack2(av, av);
        ulonglong2 w01 = *(const ulonglong2*)(cW + k * 32 + cg8);
        ulonglong2 w23 = *(const ulonglong2*)(cW + k * 32 + cg8 + 4);
        fma2(acc[0], a2, w01.x);
        fma2(acc[1], a2, w01.y);
        fma2(acc[2], a2, w23.x);
        fma2(acc[3], a2, w23.y);
    }
}

// 32-col x K256 unit, 3-stage ring. smem: sA=sm[0..6144), sW=sm[6144..9216)
__device__ __forceinline__ void mmWh(const float* A, const float* W, int cb,
                                     float* sm, ull (&acc)[4], int tid) {
    float* sA = sm;
    float* sW = sm + 6144;
    stage_A(sA, A, 0, tid); stage_W<0>(sW, W, 4096, cb, 0, tid); cpa_commit();
    stage_A(sA + 2048, A, 32, tid); stage_W<0>(sW + 1024, W, 4096, cb, 32, tid); cpa_commit();
    int b = tid & 63, cg8 = (tid >> 6) << 3;
    for (int s = 0; s < 8; s++) {
        if (s + 1 < 8) cpa_wait<1>(); else cpa_wait<0>();
        __syncthreads();
        cp_compute(sA + (s % 3) * 2048, sW + (s % 3) * 1024, b, cg8, acc);
        __syncthreads();
        if (s + 2 < 8) {
            stage_A(sA + ((s + 2) % 3) * 2048, A, (s + 2) * 32, tid);
            stage_W<0>(sW + ((s + 2) % 3) * 1024, W, 4096, cb, (s + 2) * 32, tid);
            cpa_commit();
        }
    }
}

// hyper: 40 stages (K = 1024 over g_h @ WxhH, then 256 over g_hh @ Whh)
__device__ __forceinline__ void hypStage(float* dA, float* dW, int s,
        const float* hP, const float* WxhH, const float* hhP,
        const float* Whh, int jbase, int tid) {
    const float* A; const float* W;
    if (s < 32) { A = hP + (s << 5) * 64;        W = WxhH + (s << 5) * 1024; }
    else        { A = hhP + ((s - 32) << 5) * 64; W = Whh + ((s - 32) << 5) * 1024; }
    stage_A(dA, A, 0, tid);
    stage_W<256>(dW, W, 1024, jbase, 0, tid);
    cpa_commit();
}
__device__ __forceinline__ void mmHyp(const float* hP, const float* WxhH,
                                      const float* hhP, const float* Whh,
                                      int jbase, float* sm, ull (&acc)[4], int tid) {
    float* sA = sm;
    float* sW = sm + 6144;
    hypStage(sA, sW, 0, hP, WxhH, hhP, Whh, jbase, tid);
    hypStage(sA + 2048, sW + 1024, 1, hP, WxhH, hhP, Whh, jbase, tid);
    int b = tid & 63, cg8 = (tid >> 6) << 3;
    for (int s = 0; s < 40; s++) {
        if (s + 1 < 40) cpa_wait<1>(); else cpa_wait<0>();
        __syncthreads();
        cp_compute(sA + (s % 3) * 2048, sW + (s % 3) * 1024, b, cg8, acc);
        __syncthreads();
        if (s + 2 < 40)
            hypStage(sA + ((s + 2) % 3) * 2048, sW + ((s + 2) % 3) * 1024,
                     s + 2, hP, WxhH, hhP, Whh, jbase, tid);
    }
}

// fused P2: one A (hh, K=256) vs three E weights; 2-stage ring.
// smem: sA = sm[0..4096) (2x2048), sW = sm[4096..10240) (2x3072)
__device__ __forceinline__ void mmP2(const float* A, const float* E0,
                                     const float* E1, const float* E2, int cb,
                                     float* sm, ull (&aX)[4], ull (&aH)[4],
                                     ull (&aB)[4], int tid) {
    float* sA = sm;
    float* sW = sm + 4096;
    stage_A(sA, A, 0, tid);
    stage_W<1024>(sW, E0, 4096, cb, 0, tid);
    stage_W<1024>(sW + 1024, E1, 4096, cb, 0, tid);
    stage_W<1024>(sW + 2048, E2, 4096, cb, 0, tid);
    cpa_commit();
    int b = tid & 63, cg8 = (tid >> 6) << 3;
    for (int s = 0; s < 8; s++) {
        if (s + 1 < 8) {
            float* dA = sA + ((s + 1) & 1) * 2048;
            float* dW = sW + ((s + 1) & 1) * 3072;
            stage_A(dA, A, (s + 1) * 32, tid);
            stage_W<1024>(dW, E0, 4096, cb, (s + 1) * 32, tid);
            stage_W<1024>(dW + 1024, E1, 4096, cb, (s + 1) * 32, tid);
            stage_W<1024>(dW + 2048, E2, 4096, cb, (s + 1) * 32, tid);
            cpa_commit();
            cpa_wait<1>();
        } else {
            cpa_wait<0>();
        }
        __syncthreads();
        const float* cA = sA + (s & 1) * 2048;
        const float* cW = sW + (s & 1) * 3072;
#pragma unroll
        for (int k = 0; k < 32; k++) {
            float av = cA[k * 64 + b];
            ull a2 = pack2(av, av);
            ulonglong2 x01 = *(const ulonglong2*)(cW + k * 32 + cg8);
            ulonglong2 x23 = *(const ulonglong2*)(cW + k * 32 + cg8 + 4);
            ulonglong2 h01 = *(const ulonglong2*)(cW + 1024 + k * 32 + cg8);
            ulonglong2 h23 = *(const ulonglong2*)(cW + 1024 + k * 32 + cg8 + 4);
            ulonglong2 b01 = *(const ulonglong2*)(cW + 2048 + k * 32 + cg8);
            ulonglong2 b23 = *(const ulonglong2*)(cW + 2048 + k * 32 + cg8 + 4);
            fma2(aX[0], a2, x01.x); fma2(aX[1], a2, x01.y);
            fma2(aX[2], a2, x23.x); fma2(aX[3], a2, x23.y);
            fma2(aH[0], a2, h01.x); fma2(aH[1], a2, h01.y);
            fma2(aH[2], a2, h23.x); fma2(aH[3], a2, h23.y);
            fma2(aB[0], a2, b01.x); fma2(aB[1], a2, b01.y);
            fma2(aB[2], a2, b23.x); fma2(aB[3], a2, b23.y);
        }
        __syncthreads();
    }
}

// ---------------- prologue kernels (proven) ----------------------------------
__device__ __forceinline__ void gemm_seg64(const float* __restrict__ A,
                                           const float* __restrict__ W,
                                           int K, int ldw, int colbase,
                                           float (*sA)[64], float (*sW)[64],
                                           ull (&acc)[4][2], int tid) {
    const int row = tid >> 4;
    const int q4  = (tid & 15) << 2;
    const int bg4 = (tid & 15) << 2;
    const int cg4 = (tid >> 4) << 2;
    const int nst = (K + 15) >> 4;
    const float4 f40 = make_float4(0.f, 0.f, 0.f, 0.f);

    float4 pa = (row < K) ? *(const float4*)(A + row * 64 + q4) : f40;
    float4 pw = (row < K) ? *(const float4*)(W + row * ldw + colbase + q4) : f40;

    for (int s = 0; s < nst; s++) {
        __syncthreads();
        *(float4*)(&sA[row][q4]) = pa;
        *(float4*)(&sW[row][q4]) = pw;
        __syncthreads();
        if (s + 1 < nst) {
            int kn = (s + 1) * 16 + row;
            pa = (kn < K) ? *(const float4*)(A + kn * 64 + q4) : f40;
            pw = (kn < K) ? *(const float4*)(W + kn * ldw + colbase + q4) : f40;
        }
#pragma unroll
        for (int k = 0; k < 16; k++) {
            ulonglong2 a = *(const ulonglong2*)(&sA[k][bg4]);
            float4 w = *(const float4*)(&sW[k][cg4]);
            ull w0 = pack2(w.x, w.x), w1 = pack2(w.y, w.y);
            ull w2 = pack2(w.z, w.z), w3 = pack2(w.w, w.w);
            fma2(acc[0][0], a.x, w0); fma2(acc[0][1], a.y, w0);
            fma2(acc[1][0], a.x, w1); fma2(acc[1][1], a.y, w1);
            fma2(acc[2][0], a.x, w2); fma2(acc[2][1], a.y, w2);
            fma2(acc[3][0], a.x, w3); fma2(acc[3][1], a.y, w3);
        }
    }
    __syncthreads();
}

__global__ void k_transpose(const float* __restrict__ strokes) {
    int idx = blockIdx.x * blockDim.x + threadIdx.x;
    if (idx >= NSEQ * B * IND) return;
    int t = idx / (B * IND);
    int r = idx - t * (B * IND);
    int b = r / IND;
    int k = r - b * IND;
    g_x[t][k][b] = strokes[idx];
}

__global__ void k_init(const float* __restrict__ z, const float* __restrict__ w,
                       const float* __restrict__ bias) {
    // reset barrier flags for this launch (graph replays reuse state!)
    if (blockIdx.x == 0 && threadIdx.x < GRID) g_flag[threadIdx.x] = 0u;
    int idx = blockIdx.x * blockDim.x + threadIdx.x;
    int b = idx & 63;
    int col = idx >> 6;
    if (col >= 2560) return;
    float acc = bias[col];
#pragma unroll 4
    for (int k = 0; k < 128; k++) acc += z[b * 128 + k] * w[k * 2560 + col];
    float v = tanhf(acc);
    if (col < 1024)       g_h[col][b] = v;
    else if (col < 2048)  g_c[col - 1024][b] = v;
    else if (col < 2304)  g_hh[0][col - 2048][b] = v;
    else                  g_ch[col - 2304][b] = v;
}

__global__ void __launch_bounds__(256) k_pre_ax(const float* __restrict__ Wx) {
    __shared__ __align__(16) float sm[2048];
    int t = blockIdx.y, cb = blockIdx.x * 64, tid = threadIdx.x;
    ull acc[4][2] = {};
    gemm_seg64(&g_x[t][0][0], Wx, IND, 4096, cb,
               (float(*)[64])sm, (float(*)[64])(sm + 1024), acc, tid);
    int bg4 = (tid & 15) << 2, cg4 = (tid >> 4) << 2;
#pragma unroll
    for (int c = 0; c < 4; c++) {
        ulonglong2 v; v.x = acc[c][0]; v.y = acc[c][1];
        *(ulonglong2*)(&g_axp[t][cb + cg4 + c][bg4]) = v;
    }
}

__global__ void __launch_bounds__(256) k_pre_gxh(const float* __restrict__ Wxh) {
    __shared__ __align__(16) float sm[2048];
    int t = blockIdx.y, cb = blockIdx.x * 64, tid = threadIdx.x;
    ull acc[4][2] = {};
    gemm_seg64(&g_x[t][0][0], Wxh, IND, 1024, cb,
               (float(*)[64])sm, (float(*)[64])(sm + 1024), acc, tid);
    int bg4 = (tid & 15) << 2, cg4 = (tid >> 4) << 2;
#pragma unroll
    for (int c = 0; c < 4; c++) {
        ulonglong2 v; v.x = acc[c][0]; v.y = acc[c][1];
        *(ulonglong2*)(&g_gxh[t][cb + cg4 + c][bg4]) = v;
    }
}

// E[ty][k][g*1024+j] = sum_f Wz[ty][k][g*64+f] * D[ty][g][f][j]
__global__ void __launch_bounds__(256) k_pre_E(
        const float* __restrict__ Wzx, const float* __restrict__ Wzh,
        const float* __restrict__ Wzb,
        const float* __restrict__ Dx, const float* __restrict__ Dh,
        const float* __restrict__ Db) {
    int ty = blockIdx.z, k = blockIdx.y;
    int g = blockIdx.x >> 2, jc = (blockIdx.x & 3) << 8;
    const float* Wz = (ty == 0) ? Wzx : (ty == 1) ? Wzh : Wzb;
    const float* D  = (ty == 0) ? Dx  : (ty == 1) ? Dh  : Db;
    __shared__ float sw[64];
    if (threadIdx.x < 64) sw[threadIdx.x] = Wz[k * 256 + g * 64 + threadIdx.x];
    __syncthreads();
    int j = jc + threadIdx.x;
    float acc = 0.f;
#pragma unroll 16
    for (int f = 0; f < 64; f++) acc += sw[f] * D[(g * 64 + f) * 1024 + j];
    g_E[ty][k][g * 1024 + j] = acc;
}

__global__ void k_pre_Eb(const float* __restrict__ bzx, const float* __restrict__ bzh,
                         const float* __restrict__ Dx, const float* __restrict__ Dh) {
    int idx = blockIdx.x * 256 + threadIdx.x;
    if (idx >= 8192) return;
    int ty = idx >> 12, col = idx & 4095;
    int g = col >> 10, j = col & 1023;
    const float* bb = ty ? bzh : bzx;
    const float* D  = ty ? Dh  : Dx;
    float acc = 0.f;
#pragma unroll 16
    for (int f = 0; f < 64; f++) acc += bb[g * 64 + f] * D[(g * 64 + f) * 1024 + j];
    g_Ebias[ty][col] = acc;
}

// ---------------- THE persistent recurrence kernel ---------------------------
__global__ void __launch_bounds__(256, 1) k_seq(
        const float* __restrict__ Wxh, const float* __restrict__ Whh,
        const float* __restrict__ bhy, const float* __restrict__ Wh,
        const float* __restrict__ b0) {
    // smem union: P1 mm uses [0,9216); P2 mm uses [0,10240); sPre overlays [0,2048)
    __shared__ __align__(16) float sm[10240];  // 40KB
    const int bx = blockIdx.x;
    const int tid = threadIdx.x;
    const float* WxhH = Wxh + IND * 1024;

    const int b = tid & 63;
    const int cg8 = (tid >> 6) << 3;
    unsigned ep = 0;

    for (int t = 0; t < NSEQ; t++) {
        const int cur = t & 1, nxt = cur ^ 1;

        // ===== P1: hyper gates + hyper cell (32 blocks) || h@Wh (116 blocks) =
        if (bx < 32) {
            const int jbase = bx * 8;
            const int g = cg8 >> 3;
            ull acc[4];
#pragma unroll
            for (int i = 0; i < 4; i++) {
                int c0 = (g << 8) + jbase + 2 * i;
                acc[i] = pack2(g_gxh[t][c0][b], g_gxh[t][c0 + 1][b]);
            }
            mmHyp(&g_h[0][0], WxhH, &g_hh[cur][0][0], Whh, jbase, sm, acc, tid);

            float* sPre = sm;  // 2048 floats, free after pipeline drains
#pragma unroll
            for (int i = 0; i < 4; i++) {
                int c0 = (g << 8) + jbase + 2 * i;
                ull p = add2(acc[i], pack2(bhy[c0], bhy[c0 + 1]));
                float lo, hi; unpack2(p, lo, hi);
                sPre[(g * 8 + 2 * i) * 64 + b] = lo;
                sPre[(g * 8 + 2 * i + 1) * 64 + b] = hi;
            }
            __syncthreads();
#pragma unroll
            for (int r = 0; r < 2; r++) {
                int idx = tid + (r << 8);
                int jl = idx >> 6, bb = idx & 63;
                int jg = jbase + jl;
                float iv = sPre[jl * 64 + bb];
                float fv = sPre[(8 + jl) * 64 + bb];
                float gv = sPre[(16 + jl) * 64 + bb];
                float ov = sPre[(24 + jl) * 64 + bb];
                float chv = sigf(fv) * g_ch[jg][bb] + sigf(iv) * tanhf(gv);
                g_ch[jg][bb] = chv;
                g_hh[nxt][jg][bb] = sigf(ov) * tanhf(chv);
            }
        } else {
            // h @ Wh : 512 units of (32 cols, K=256). 48 blocks x5, 68 blocks x4.
            int w0 = bx - 32;
            int start = (w0 < 48) ? w0 * 5 : 240 + (w0 - 48) * 4;
            int cnt = (w0 < 48) ? 5 : 4;
            for (int i = 0; i < cnt; i++) {
                int u = start + i;
                int ct = u >> 2, ks = u & 3;
                ull acc[4] = {};
                mmWh(&g_h[ks * 256][0], Wh + ks * 256 * 4096, ct * 32, sm, acc, tid);
#pragma unroll
                for (int c = 0; c < 4; c++) {
                    int c0 = ct * 32 + cg8 + 2 * c;
                    float lo, hi; unpack2(acc[c], lo, hi);
                    g_ahp[ks][c0][b] = lo;
                    g_ahp[ks][c0 + 1][b] = hi;
                }
            }
        }
        ep++; grid_bar(ep, bx, tid);

        // ===== P2: sx/sh/sb = hh@E (+Eb), combine, main cell (128 blocks) =====
        if (bx < 128) {
            const int jb = bx;  // j in [jb*8, jb*8+8)
            const int g = cg8 >> 3;
            ull aX[4] = {}, aH[4] = {}, aB[4] = {};
            mmP2(&g_hh[nxt][0][0], &g_E[0][0][0], &g_E[1][0][0], &g_E[2][0][0],
                 jb * 8, sm, aX, aH, aB, tid);

            float* sPre = sm;  // overlays stage buffers (drained)
#pragma unroll
            for (int i = 0; i < 4; i++) {
                int c0 = g * 1024 + jb * 8 + 2 * i;
                int c1 = c0 + 1;
                ull ax = pack2(g_axp[t][c0][b], g_axp[t][c1][b]);
                ull ah = add2(add2(pack2(g_ahp[0][c0][b], g_ahp[0][c1][b]),
                                   pack2(g_ahp[1][c0][b], g_ahp[1][c1][b])),
                              add2(pack2(g_ahp[2][c0][b], g_ahp[2][c1][b]),
                                   pack2(g_ahp[3][c0][b], g_ahp[3][c1][b])));
                ull sxv = add2(aX[i], pack2(g_Ebias[0][c0], g_Ebias[0][c1]));
                ull shv = add2(aH[i], pack2(g_Ebias[1][c0], g_Ebias[1][c1]));
                ull p = mul2(sxv, ax);
                fma2(p, shv, ah);
                p = add2(p, aB[i]);
                p = add2(p, pack2(b0[c0], b0[c1]));
                float lo, hi; unpack2(p, lo, hi);
                sPre[(g * 8 + 2 * i) * 64 + b] = lo;
                sPre[(g * 8 + 2 * i + 1) * 64 + b] = hi;
            }
            __syncthreads();

#pragma unroll
            for (int r = 0; r < 2; r++) {
                int idx = tid + (r << 8);
                int jl = idx >> 6, bb = idx & 63;
                int jg = jb * 8 + jl;
                float iv = sPre[(0 * 8 + jl) * 64 + bb];
                float fv = sPre[(1 * 8 + jl) * 64 + bb];
                float gv = sPre[(2 * 8 + jl) * 64 + bb];
                float ov = sPre[(3 * 8 + jl) * 64 + bb];
                float cv = sigf(fv) * g_c[jg][bb] + sigf(iv) * tanhf(gv);
                g_c[jg][bb] = cv;
                float hn = sigf(ov) * tanhf(cv);
                g_h[jg][bb] = hn;
                g_outs[t][jg][bb] = hn;
            }
        }
        ep++; grid_bar(ep, bx, tid);
    }
}

// ---------------- epilogue ---------------------------------------------------
__global__ void __launch_bounds__(256) k_proj(const float* __restrict__ Wp,
                                              const float* __restrict__ bp) {
    __shared__ __align__(16) float smem[2048];
    float (*sA)[64] = (float(*)[64])smem;
    float (*sW)[64] = (float(*)[64])(smem + 1024);
    int t = blockIdx.y;
    int cb = blockIdx.x * 64;
    int tid = threadIdx.x;
    const float* A = &g_outs[t][0][0];
    const int row = tid >> 4;
    const int q4 = (tid & 15) << 2;
    const int bg4 = (tid & 15) << 2;
    const int cg4 = (tid >> 4) << 2;
    ull acc[4][2] = {};

    float4 pa = *(const float4*)(A + row * 64 + q4);
    float4 pw;
    {
        const float* wr = Wp + row * OUTD + cb + q4;
        pw.x = (cb + q4 + 0 < OUTD) ? wr[0] : 0.f;
        pw.y = (cb + q4 + 1 < OUTD) ? wr[1] : 0.f;
        pw.z = (cb + q4 + 2 < OUTD) ? wr[2] : 0.f;
        pw.w = (cb + q4 + 3 < OUTD) ? wr[3] : 0.f;
    }
    for (int s = 0; s < 64; s++) {
        __syncthreads();
        *(float4*)(&sA[row][q4]) = pa;
        *(float4*)(&sW[row][q4]) = pw;
        __syncthreads();
        if (s + 1 < 64) {
            int kn = (s + 1) * 16 + row;
            pa = *(const float4*)(A + kn * 64 + q4);
            const float* wr = Wp + kn * OUTD + cb + q4;
            pw.x = (cb + q4 + 0 < OUTD) ? wr[0] : 0.f;
            pw.y = (cb + q4 + 1 < OUTD) ? wr[1] : 0.f;
            pw.z = (cb + q4 + 2 < OUTD) ? wr[2] : 0.f;
            pw.w = (cb + q4 + 3 < OUTD) ? wr[3] : 0.f;
        }
#pragma unroll
        for (int k = 0; k < 16; k++) {
            ulonglong2 a = *(const ulonglong2*)(&sA[k][bg4]);
            float4 w = *(const float4*)(&sW[k][cg4]);
            ull w0 = pack2(w.x, w.x), w1 = pack2(w.y, w.y);
            ull w2 = pack2(w.z, w.z), w3 = pack2(w.w, w.w);
            fma2(acc[0][0], a.x, w0); fma2(acc[0][1], a.y, w0);
            fma2(acc[1][0], a.x, w1); fma2(acc[1][1], a.y, w1);
            fma2(acc[2][0], a.x, w2); fma2(acc[2][1], a.y, w2);
            fma2(acc[3][0], a.x, w3); fma2(acc[3][1], a.y, w3);
        }
    }
#pragma unroll
    for (int c = 0; c < 4; c++) {
        int col = cb + cg4 + c;
        if (col < OUTD) {
            float bv = bp[col];
            ull bpp = pack2(bv, bv);
            ulonglong2 v;
            v.x = add2(acc[c][0], bpp);
            v.y = add2(acc[c][1], bpp);
            *(ulonglong2*)(&g_dec[t][col][bg4]) = v;
        }
    }
}

__global__ void k_mdn(float* __restrict__ out) {
    int idx = blockIdx.x * blockDim.x + threadIdx.x;
    if (idx >= NSEQ * B * 21) return;
    int u = idx % 21;
    int r = idx / 21;
    int b = r & 63;
    int t = r >> 6;
    if (u < 20) {
        int m = u;
        int off = t * 20 * 64 + m * 64 + b;
        out[off] = 1.0f;
        out[163840 + off] = g_dec[t][6 * m + 1][b];
        out[327680 + off] = g_dec[t][6 * m + 2][b];
        out[491520 + off] = expf(g_dec[t][6 * m + 3][b]);
        out[655360 + off] = expf(g_dec[t][6 * m + 4][b]);
        out[819200 + off] = tanhf(g_dec[t][6 * m + 5][b]);
    } else {
        float p0 = g_dec[t][120][b], p1 = g_dec[t][121][b], p2 = g_dec[t][122][b];
        float mx = fmaxf(p0, fmaxf(p1, p2));
        float e0 = expf(p0 - mx), e1 = expf(p1 - mx), e2 = expf(p2 - mx);
        float s = e0 + e1 + e2;
        int base = 983040 + t * (B * 3) + b * 3;
        out[base + 0] = e0 / s;
        out[base + 1] = e1 / s;
        out[base + 2] = e2 / s;
    }
}

// ---------------- host driver ------------------------------------------------
extern "C" void kernel_launch(void* const* d_in, const int* in_sizes, int n_in,
                              void* d_out, int out_size) {
    const float* z        = (const float*)d_in[0];
    const float* strokes  = (const float*)d_in[1];
    const float* fc_in_w  = (const float*)d_in[2];
    const float* fc_in_b  = (const float*)d_in[3];
    const float* fc_proj_w= (const float*)d_in[4];
    const float* fc_proj_b= (const float*)d_in[5];
    const float* Wx       = (const float*)d_in[6];
    const float* Wh       = (const float*)d_in[7];
    const float* b0       = (const float*)d_in[8];
    const float* Wxh      = (const float*)d_in[9];
    const float* Whh      = (const float*)d_in[10];
    const float* bhy      = (const float*)d_in[11];
    const float* Wzx      = (const float*)d_in[12];
    const float* bzx      = (const float*)d_in[13];
    const float* Wzh      = (const float*)d_in[14];
    const float* bzh      = (const float*)d_in[15];
    const float* Wzb      = (const float*)d_in[16];
    const float* Dx       = (const float*)d_in[17];
    const float* Dh       = (const float*)d_in[18];
    const float* Db       = (const float*)d_in[19];
    float* out = (float*)d_out;

    k_transpose<<<(NSEQ * B * IND + 255) / 256, 256>>>(strokes);
    k_init<<<(B * 2560 + 255) / 256, 256>>>(z, fc_in_w, fc_in_b);
    k_pre_ax<<<dim3(64, NSEQ), 256>>>(Wx);
    k_pre_gxh<<<dim3(16, NSEQ), 256>>>(Wxh);
    k_pre_E<<<dim3(16, HY, 3), 256>>>(Wzx, Wzh, Wzb, Dx, Dh, Db);
    k_pre_Eb<<<32, 256>>>(bzx, bzh, Dx, Dh);

    k_seq<<<GRID, 256>>>(Wxh, Whh, bhy, Wh, b0);

    dim3 pg(2, NSEQ);
    k_proj<<<pg, 256>>>(fc_proj_w, fc_proj_b);
    k_mdn<<<(NSEQ * B * 21 + 255) / 256, 256>>>(out);
}

// round 13
// speedup vs baseline: 1.0505x; 1.0505x over previous
#include <cuda_runtime.h>
#include <math.h>
#include <stdint.h>

typedef unsigned long long ull;

#define B 64
#define H 1024
#define HY 256
#define F 64
#define IND 133
#define NSEQ 128
#define OUTD 123
#define GRID 148

// ---------------- persistent device state ----------------------------------
__device__ __align__(16) float g_h[H][B];
__device__ __align__(16) float g_c[H][B];
__device__ __align__(16) float g_hh[2][HY][B];
__device__ __align__(16) float g_ch[HY][B];
__device__ __align__(16) float g_z[3 * HY][B];
__device__ __align__(16) float g_ahp[4][4 * H][B];      // h@Wh split-K partials
__device__ __align__(16) float g_x[NSEQ][IND][B];
__device__ __align__(16) float g_axp[NSEQ][4 * H][B];   // precomputed x@Wx
__device__ __align__(16) float g_gxh[NSEQ][4 * HY][B];  // precomputed x@Wxh(x-rows)
__device__ __align__(16) float g_outs[NSEQ][H][B];
__device__ __align__(16) float g_dec[NSEQ][OUTD][B];
__device__ unsigned g_bar_count;
__device__ unsigned g_bar_gen;

__device__ __forceinline__ float sigf(float x) { return 1.0f / (1.0f + expf(-x)); }

__device__ __forceinline__ void fma2(ull& d, ull a, ull b) {
    asm("fma.rn.f32x2 %0, %1, %2, %0;" : "+l"(d) : "l"(a), "l"(b));
}
__device__ __forceinline__ ull mul2(ull a, ull b) {
    ull d; asm("mul.rn.f32x2 %0, %1, %2;" : "=l"(d) : "l"(a), "l"(b)); return d;
}
__device__ __forceinline__ ull add2(ull a, ull b) {
    ull d; asm("add.rn.f32x2 %0, %1, %2;" : "=l"(d) : "l"(a), "l"(b)); return d;
}
__device__ __forceinline__ ull pack2(float x, float y) {
    ull r; asm("mov.b64 %0, {%1, %2};" : "=l"(r) : "f"(x), "f"(y)); return r;
}
__device__ __forceinline__ void unpack2(ull v, float& lo, float& hi) {
    asm("mov.b64 {%0, %1}, %2;" : "=f"(lo), "=f"(hi) : "l"(v));
}

// ---------------- cp.async helpers ------------------------------------------
__device__ __forceinline__ void cpa16(void* dst, const void* src) {
    unsigned d = (unsigned)__cvta_generic_to_shared(dst);
    asm volatile("cp.async.cg.shared.global [%0], [%1], 16;" :: "r"(d), "l"(src));
}
__device__ __forceinline__ void cpa_commit() {
    asm volatile("cp.async.commit_group;");
}
template<int N>
__device__ __forceinline__ void cpa_wait() {
    asm volatile("cp.async.wait_group %0;" :: "n"(N));
}

// ---------------- grid-wide barrier (R9 proven version) ----------------------
__device__ __forceinline__ void grid_bar() {
    __syncthreads();
    if (threadIdx.x == 0) {
        unsigned gen = *(volatile unsigned*)&g_bar_gen;
        __threadfence();
        unsigned arr = atomicAdd(&g_bar_count, 1u);
        if (arr == GRID - 1) {
            *(volatile unsigned*)&g_bar_count = 0u;
            __threadfence();
            *(volatile unsigned*)&g_bar_gen = gen + 1u;
        } else {
            while (*(volatile unsigned*)&g_bar_gen == gen) {}
        }
        __threadfence();
    }
    __syncthreads();
}

// ---------------- double-buffered 32-col GEMM core (col-pair inner) ----------
// Thread mapping: b = tid & 63 (one batch), cg8 = (tid>>6)*8 (8 local cols).
// acc[i] = f32x2 over local cols (cg8+2i, cg8+2i+1) for batch b.
// GATHER: local col c maps to W col ((c>>3)<<8) + cb + (c&7) (4 gate groups of 8).
// smem: sA = sm[0..4096) (2x2048), sW = sm[4096..6144) (2x1024).
template<bool GATHER>
__device__ __forceinline__ void mm32(const float* __restrict__ A,
                                     const float* __restrict__ W,
                                     int ldw, int cb, int nst,
                                     float* sm, ull (&acc)[4], int tid) {
    float* sA = sm;
    float* sW = sm + 4096;
    const int ar  = tid >> 4;
    const int ac4 = (tid & 15) << 2;
    const int wr  = tid >> 3;
    const int wq  = tid & 7;
    const int b   = tid & 63;
    const int cg8 = (tid >> 6) << 3;

    // stage 0 loads
    {
        cpa16(sA + ar * 64 + ac4, A + ar * 64 + ac4);
        cpa16(sA + (ar + 16) * 64 + ac4, A + (ar + 16) * 64 + ac4);
        const float* ws = GATHER
            ? (W + wr * ldw + ((wq >> 1) << 8) + cb + ((wq & 1) << 2))
            : (W + wr * ldw + cb + (wq << 2));
        cpa16(sW + wr * 32 + (wq << 2), ws);
        cpa_commit();
    }
    for (int s = 0; s < nst; s++) {
        int buf = s & 1;
        if (s + 1 < nst) {
            int k0 = (s + 1) << 5;
            float* dA = sA + (buf ^ 1) * 2048;
            float* dW = sW + (buf ^ 1) * 1024;
            cpa16(dA + ar * 64 + ac4, A + (k0 + ar) * 64 + ac4);
            cpa16(dA + (ar + 16) * 64 + ac4, A + (k0 + ar + 16) * 64 + ac4);
            const float* ws = GATHER
                ? (W + (k0 + wr) * ldw + ((wq >> 1) << 8) + cb + ((wq & 1) << 2))
                : (W + (k0 + wr) * ldw + cb + (wq << 2));
            cpa16(dW + wr * 32 + (wq << 2), ws);
            cpa_commit();
            cpa_wait<1>();
        } else {
            cpa_wait<0>();
        }
        __syncthreads();
        const float* cA = sA + buf * 2048;
        const float* cW = sW + buf * 1024;
#pragma unroll
        for (int k = 0; k < 32; k++) {
            float av = cA[k * 64 + b];
            ull a2 = pack2(av, av);
            ulonglong2 w01 = *(const ulonglong2*)(cW + k * 32 + cg8);
            ulonglong2 w23 = *(const ulonglong2*)(cW + k * 32 + cg8 + 4);
            fma2(acc[0], a2, w01.x);
            fma2(acc[1], a2, w01.y);
            fma2(acc[2], a2, w23.x);
            fma2(acc[3], a2, w23.y);
        }
        __syncthreads();
    }
}

// ---------------- prologue kernels (unchanged, proven) -----------------------
__device__ __forceinline__ void gemm_seg64(const float* __restrict__ A,
                                           const float* __restrict__ W,
                                           int K, int ldw, int colbase,
                                           float (*sA)[64], float (*sW)[64],
                                           ull (&acc)[4][2], int tid) {
    const int row = tid >> 4;
    const int q4  = (tid & 15) << 2;
    const int bg4 = (tid & 15) << 2;
    const int cg4 = (tid >> 4) << 2;
    const int nst = (K + 15) >> 4;
    const float4 f40 = make_float4(0.f, 0.f, 0.f, 0.f);

    float4 pa = (row < K) ? *(const float4*)(A + row * 64 + q4) : f40;
    float4 pw = (row < K) ? *(const float4*)(W + row * ldw + colbase + q4) : f40;

    for (int s = 0; s < nst; s++) {
        __syncthreads();
        *(float4*)(&sA[row][q4]) = pa;
        *(float4*)(&sW[row][q4]) = pw;
        __syncthreads();
        if (s + 1 < nst) {
            int kn = (s + 1) * 16 + row;
            pa = (kn < K) ? *(const float4*)(A + kn * 64 + q4) : f40;
            pw = (kn < K) ? *(const float4*)(W + kn * ldw + colbase + q4) : f40;
        }
#pragma unroll
        for (int k = 0; k < 16; k++) {
            ulonglong2 a = *(const ulonglong2*)(&sA[k][bg4]);
            float4 w = *(const float4*)(&sW[k][cg4]);
            ull w0 = pack2(w.x, w.x), w1 = pack2(w.y, w.y);
            ull w2 = pack2(w.z, w.z), w3 = pack2(w.w, w.w);
            fma2(acc[0][0], a.x, w0); fma2(acc[0][1], a.y, w0);
            fma2(acc[1][0], a.x, w1); fma2(acc[1][1], a.y, w1);
            fma2(acc[2][0], a.x, w2); fma2(acc[2][1], a.y, w2);
            fma2(acc[3][0], a.x, w3); fma2(acc[3][1], a.y, w3);
        }
    }
    __syncthreads();
}

__global__ void k_transpose(const float* __restrict__ strokes) {
    int idx = blockIdx.x * blockDim.x + threadIdx.x;
    if (idx >= NSEQ * B * IND) return;
    int t = idx / (B * IND);
    int r = idx - t * (B * IND);
    int b = r / IND;
    int k = r - b * IND;
    g_x[t][k][b] = strokes[idx];
}

__global__ void k_init(const float* __restrict__ z, const float* __restrict__ w,
                       const float* __restrict__ bias) {
    int idx = blockIdx.x * blockDim.x + threadIdx.x;
    int b = idx & 63;
    int col = idx >> 6;
    if (col >= 2560) return;
    float acc = bias[col];
#pragma unroll 4
    for (int k = 0; k < 128; k++) acc += z[b * 128 + k] * w[k * 2560 + col];
    float v = tanhf(acc);
    if (col < 1024)       g_h[col][b] = v;
    else if (col < 2048)  g_c[col - 1024][b] = v;
    else if (col < 2304)  g_hh[0][col - 2048][b] = v;
    else                  g_ch[col - 2304][b] = v;
}

__global__ void __launch_bounds__(256) k_pre_ax(const float* __restrict__ Wx) {
    __shared__ __align__(16) float sm[2048];
    int t = blockIdx.y, cb = blockIdx.x * 64, tid = threadIdx.x;
    ull acc[4][2] = {};
    gemm_seg64(&g_x[t][0][0], Wx, IND, 4096, cb,
               (float(*)[64])sm, (float(*)[64])(sm + 1024), acc, tid);
    int bg4 = (tid & 15) << 2, cg4 = (tid >> 4) << 2;
#pragma unroll
    for (int c = 0; c < 4; c++) {
        ulonglong2 v; v.x = acc[c][0]; v.y = acc[c][1];
        *(ulonglong2*)(&g_axp[t][cb + cg4 + c][bg4]) = v;
    }
}

__global__ void __launch_bounds__(256) k_pre_gxh(const float* __restrict__ Wxh) {
    __shared__ __align__(16) float sm[2048];
    int t = blockIdx.y, cb = blockIdx.x * 64, tid = threadIdx.x;
    ull acc[4][2] = {};
    gemm_seg64(&g_x[t][0][0], Wxh, IND, 1024, cb,
               (float(*)[64])sm, (float(*)[64])(sm + 1024), acc, tid);
    int bg4 = (tid & 15) << 2, cg4 = (tid >> 4) << 2;
#pragma unroll
    for (int c = 0; c < 4; c++) {
        ulonglong2 v; v.x = acc[c][0]; v.y = acc[c][1];
        *(ulonglong2*)(&g_gxh[t][cb + cg4 + c][bg4]) = v;
    }
}

// ---------------- THE persistent recurrence kernel ---------------------------
__global__ void __launch_bounds__(256, 1) k_seq(
        const float* __restrict__ Wxh, const float* __restrict__ Whh,
        const float* __restrict__ bhy, const float* __restrict__ Wh,
        const float* __restrict__ Wzx, const float* __restrict__ bzx,
        const float* __restrict__ Wzh, const float* __restrict__ bzh,
        const float* __restrict__ Wzb, const float* __restrict__ b0,
        const float* __restrict__ Dx, const float* __restrict__ Dh,
        const float* __restrict__ Db) {
    // union: phases A/B: mm32 [0,6144), sT [6144,8192); phase C:
    // sZ [0,6144), sWD [6144,7680), sPre [7680,11776)  -> 47KB
    __shared__ __align__(16) float sm[11776];
    const int bx = blockIdx.x;
    const int tid = threadIdx.x;
    const float* WxhH = Wxh + IND * 1024;

    const int b = tid & 63;
    const int cg8 = (tid >> 6) << 3;

    for (int t = 0; t < NSEQ; t++) {
        const int cur = t & 1, nxt = cur ^ 1;

        // ================= phase A: hyper (32 blocks) || h@Wh (116 blocks) ===
        if (bx < 32) {
            const int jbase = bx * 8;
            const int g = cg8 >> 3;
            ull acc[4];
#pragma unroll
            for (int i = 0; i < 4; i++) {
                int c0 = (g << 8) + jbase + 2 * i;
                acc[i] = pack2(g_gxh[t][c0][b], g_gxh[t][c0 + 1][b]);
            }
            mm32<true>(&g_h[0][0],       WxhH, 1024, jbase, 32, sm, acc, tid);
            mm32<true>(&g_hh[cur][0][0], Whh,  1024, jbase, 8,  sm, acc, tid);

            float* sPre = sm;  // 2048 floats (free after mm32)
#pragma unroll
            for (int i = 0; i < 4; i++) {
                int c0 = (g << 8) + jbase + 2 * i;
                ull p = add2(acc[i], pack2(bhy[c0], bhy[c0 + 1]));
                float lo, hi; unpack2(p, lo, hi);
                sPre[(g * 8 + 2 * i) * 64 + b] = lo;
                sPre[(g * 8 + 2 * i + 1) * 64 + b] = hi;
            }
            __syncthreads();
#pragma unroll
            for (int r = 0; r < 2; r++) {
                int idx = tid + (r << 8);
                int jl = idx >> 6, bb = idx & 63;
                int jg = jbase + jl;
                float iv = sPre[jl * 64 + bb];
                float fv = sPre[(8 + jl) * 64 + bb];
                float gv = sPre[(16 + jl) * 64 + bb];
                float ov = sPre[(24 + jl) * 64 + bb];
                float chv = sigf(fv) * g_ch[jg][bb] + sigf(iv) * tanhf(gv);
                g_ch[jg][bb] = chv;
                g_hh[nxt][jg][bb] = sigf(ov) * tanhf(chv);
            }
        } else {
            // h @ Wh : 512 units of (32 cols, K=256). 48 blocks x5, 68 blocks x4.
            int w0 = bx - 32;
            int start = (w0 < 48) ? w0 * 5 : 240 + (w0 - 48) * 4;
            int cnt = (w0 < 48) ? 5 : 4;
            for (int i = 0; i < cnt; i++) {
                int u = start + i;
                int ct = u >> 2, ks = u & 3;
                ull acc[4] = {};
                mm32<false>(&g_h[ks * 256][0], Wh + ks * 256 * 4096, 4096,
                            ct * 32, 8, sm, acc, tid);
                // epilogue: smem transpose tile, then vectorized 16B stores
                float* sT = sm + 6144;
#pragma unroll
                for (int c = 0; c < 4; c++) {
                    float lo, hi; unpack2(acc[c], lo, hi);
                    sT[(cg8 + 2 * c) * 64 + b] = lo;
                    sT[(cg8 + 2 * c + 1) * 64 + b] = hi;
                }
                __syncthreads();
                int row = tid >> 3, off = (tid & 7) << 3;
                ulonglong2 v0 = *(const ulonglong2*)(sT + row * 64 + off);
                ulonglong2 v1 = *(const ulonglong2*)(sT + row * 64 + off + 4);
                *(ulonglong2*)(&g_ahp[ks][ct * 32 + row][off]) = v0;
                *(ulonglong2*)(&g_ahp[ks][ct * 32 + row][off + 4]) = v1;
            }
        }
        grid_bar();

        // ================= phase B: z projections (24 blocks) ================
        if (bx < 24) {
            int type = bx >> 3, cb = (bx & 7) * 32;
            const float* W = (type == 0) ? Wzx : (type == 1) ? Wzh : Wzb;
            ull acc[4] = {};
            mm32<false>(&g_hh[nxt][0][0], W, 256, cb, 8, sm, acc, tid);
            float* sT = sm + 6144;
#pragma unroll
            for (int c = 0; c < 4; c++) {
                int col = cb + cg8 + 2 * c;
                float b0v = (type == 0) ? bzx[col] : (type == 1) ? bzh[col] : 0.0f;
                float b1v = (type == 0) ? bzx[col + 1] : (type == 1) ? bzh[col + 1] : 0.0f;
                ull p = add2(acc[c], pack2(b0v, b1v));
                float lo, hi; unpack2(p, lo, hi);
                sT[(cg8 + 2 * c) * 64 + b] = lo;
                sT[(cg8 + 2 * c + 1) * 64 + b] = hi;
            }
            __syncthreads();
            int row = tid >> 3, off = (tid & 7) << 3;
            ulonglong2 v0 = *(const ulonglong2*)(sT + row * 64 + off);
            ulonglong2 v1 = *(const ulonglong2*)(sT + row * 64 + off + 4);
            *(ulonglong2*)(&g_z[type * 256 + cb + row][off]) = v0;
            *(ulonglong2*)(&g_z[type * 256 + cb + row][off + 4]) = v1;
        }
        grid_bar();

        // ================= phase C: einsums + combine + cell (64 blocks) =====
        if (bx < 64) {
            const int jt = bx;
            const int bg4 = (tid & 15) << 2;
            const int cg16 = tid >> 4;          // 0..15 -> 4 local cols
            const int gate = cg16 >> 2;
            const int j4 = (cg16 & 3) << 2;

            ull sx[4][2] = {}, sh[4][2] = {}, sb[4][2] = {};

            // stage loader: f-chunk of 4; sZ[ty][g][fr][64]  sWD[ty][fr][64]
            {
                int f0 = 0;
#pragma unroll
                for (int p = 0; p < 3; p++) {
                    int i = tid + (p << 8);
                    int b4 = (i & 15) << 2;
                    int r = i >> 4;
                    int fr = r & 3, g = (r >> 2) & 3, ty = r >> 4;
                    cpa16(sm + ((ty * 4 + g) * 4 + fr) * 64 + b4,
                          &g_z[ty * 256 + g * 64 + f0 + fr][b4]);
                }
                if (tid < 192) {
                    int ty = tid >> 6, rem = tid & 63;
                    int fr = rem >> 4, c4 = (rem & 15) << 2;
                    const float* D = (ty == 0) ? Dx : (ty == 1) ? Dh : Db;
                    cpa16(sm + 6144 + (ty * 4 + fr) * 64 + c4,
                          D + ((c4 >> 4) * 64 + f0 + fr) * 1024 + jt * 16 + (c4 & 15));
                }
                cpa_commit();
            }
            for (int st = 0; st < 16; st++) {
                int buf = st & 1;
                if (st + 1 < 16) {
                    int f0 = (st + 1) << 2;
                    float* dZ = sm + (buf ^ 1) * 3072;
                    float* dW = sm + 6144 + (buf ^ 1) * 768;
#pragma unroll
                    for (int p = 0; p < 3; p++) {
                        int i = tid + (p << 8);
                        int b4 = (i & 15) << 2;
                        int r = i >> 4;
                        int fr = r & 3, g = (r >> 2) & 3, ty = r >> 4;
                        cpa16(dZ + ((ty * 4 + g) * 4 + fr) * 64 + b4,
                              &g_z[ty * 256 + g * 64 + f0 + fr][b4]);
                    }
                    if (tid < 192) {
                        int ty = tid >> 6, rem = tid & 63;
                        int fr = rem >> 4, c4 = (rem & 15) << 2;
                        const float* D = (ty == 0) ? Dx : (ty == 1) ? Dh : Db;
                        cpa16(dW + (ty * 4 + fr) * 64 + c4,
                              D + ((c4 >> 4) * 64 + f0 + fr) * 1024 + jt * 16 + (c4 & 15));
                    }
                    cpa_commit();
                    cpa_wait<1>();
                } else {
                    cpa_wait<0>();
                }
                __syncthreads();
                const float* cZ = sm + buf * 3072;
                const float* cW = sm + 6144 + buf * 768;
#pragma unroll
                for (int k = 0; k < 4; k++) {
                    ulonglong2 azx = *(const ulonglong2*)(cZ + ((0 * 4 + gate) * 4 + k) * 64 + bg4);
                    ulonglong2 azh = *(const ulonglong2*)(cZ + ((1 * 4 + gate) * 4 + k) * 64 + bg4);
                    ulonglong2 azb = *(const ulonglong2*)(cZ + ((2 * 4 + gate) * 4 + k) * 64 + bg4);
                    float4 wx = *(const float4*)(cW + (0 * 4 + k) * 64 + cg16 * 4);
                    float4 wh = *(const float4*)(cW + (1 * 4 + k) * 64 + cg16 * 4);
                    float4 wb = *(const float4*)(cW + (2 * 4 + k) * 64 + cg16 * 4);
#pragma unroll
                    for (int c = 0; c < 4; c++) {
                        float wxc = (c == 0) ? wx.x : (c == 1) ? wx.y : (c == 2) ? wx.z : wx.w;
                        float whc = (c == 0) ? wh.x : (c == 1) ? wh.y : (c == 2) ? wh.z : wh.w;
                        float wbc = (c == 0) ? wb.x : (c == 1) ? wb.y : (c == 2) ? wb.z : wb.w;
                        ull wxp = pack2(wxc, wxc), whp = pack2(whc, whc), wbp = pack2(wbc, wbc);
                        fma2(sx[c][0], azx.x, wxp); fma2(sx[c][1], azx.y, wxp);
                        fma2(sh[c][0], azh.x, whp); fma2(sh[c][1], azh.y, whp);
                        fma2(sb[c][0], azb.x, wbp); fma2(sb[c][1], azb.y, wbp);
                    }
                }
                __syncthreads();
            }

            float* sPre = sm + 7680;  // 4096 floats: [64 cols][64 batch]
#pragma unroll
            for (int c = 0; c < 4; c++) {
                int jglob = jt * 16 + j4 + c;
                int col = gate * 1024 + jglob;
                ulonglong2 ax = *(const ulonglong2*)(&g_axp[t][col][bg4]);
                ulonglong2 a0 = *(const ulonglong2*)(&g_ahp[0][col][bg4]);
                ulonglong2 a1 = *(const ulonglong2*)(&g_ahp[1][col][bg4]);
                ulonglong2 a2 = *(const ulonglong2*)(&g_ahp[2][col][bg4]);
                ulonglong2 a3 = *(const ulonglong2*)(&g_ahp[3][col][bg4]);
                ull ahx = add2(add2(a0.x, a1.x), add2(a2.x, a3.x));
                ull ahy = add2(add2(a0.y, a1.y), add2(a2.y, a3.y));
                float bv = b0[gate * 1024 + jglob];
                ull bp = pack2(bv, bv);
                ull p0 = mul2(sx[c][0], ax.x); fma2(p0, sh[c][0], ahx);
                p0 = add2(p0, sb[c][0]); p0 = add2(p0, bp);
                ull p1 = mul2(sx[c][1], ax.y); fma2(p1, sh[c][1], ahy);
                p1 = add2(p1, sb[c][1]); p1 = add2(p1, bp);
                *(ull*)(&sPre[(gate * 16 + j4 + c) * 64 + bg4]) = p0;
                *(ull*)(&sPre[(gate * 16 + j4 + c) * 64 + bg4 + 2]) = p1;
            }
            __syncthreads();

#pragma unroll
            for (int r = 0; r < 4; r++) {
                int idx = tid + (r << 8);
                int jl = idx >> 6, bb = idx & 63;
                int jg = jt * 16 + jl;
                float iv = sPre[(0 * 16 + jl) * 64 + bb];
                float fv = sPre[(1 * 16 + jl) * 64 + bb];
                float gv = sPre[(2 * 16 + jl) * 64 + bb];
                float ov = sPre[(3 * 16 + jl) * 64 + bb];
                float cv = sigf(fv) * g_c[jg][bb] + sigf(iv) * tanhf(gv);
                g_c[jg][bb] = cv;
                float hn = sigf(ov) * tanhf(cv);
                g_h[jg][bb] = hn;
                g_outs[t][jg][bb] = hn;
            }
        }
        grid_bar();
    }
}

// ---------------- epilogue ---------------------------------------------------
__global__ void __launch_bounds__(256) k_proj(const float* __restrict__ Wp,
                                              const float* __restrict__ bp) {
    __shared__ __align__(16) float smem[2048];
    float (*sA)[64] = (float(*)[64])smem;
    float (*sW)[64] = (float(*)[64])(smem + 1024);
    int t = blockIdx.y;
    int cb = blockIdx.x * 64;
    int tid = threadIdx.x;
    const float* A = &g_outs[t][0][0];
    const int row = tid >> 4;
    const int q4 = (tid & 15) << 2;
    const int bg4 = (tid & 15) << 2;
    const int cg4 = (tid >> 4) << 2;
    ull acc[4][2] = {};

    float4 pa = *(const float4*)(A + row * 64 + q4);
    float4 pw;
    {
        const float* wr = Wp + row * OUTD + cb + q4;
        pw.x = (cb + q4 + 0 < OUTD) ? wr[0] : 0.f;
        pw.y = (cb + q4 + 1 < OUTD) ? wr[1] : 0.f;
        pw.z = (cb + q4 + 2 < OUTD) ? wr[2] : 0.f;
        pw.w = (cb + q4 + 3 < OUTD) ? wr[3] : 0.f;
    }
    for (int s = 0; s < 64; s++) {
        __syncthreads();
        *(float4*)(&sA[row][q4]) = pa;
        *(float4*)(&sW[row][q4]) = pw;
        __syncthreads();
        if (s + 1 < 64) {
            int kn = (s + 1) * 16 + row;
            pa = *(const float4*)(A + kn * 64 + q4);
            const float* wr = Wp + kn * OUTD + cb + q4;
            pw.x = (cb + q4 + 0 < OUTD) ? wr[0] : 0.f;
            pw.y = (cb + q4 + 1 < OUTD) ? wr[1] : 0.f;
            pw.z = (cb + q4 + 2 < OUTD) ? wr[2] : 0.f;
            pw.w = (cb + q4 + 3 < OUTD) ? wr[3] : 0.f;
        }
#pragma unroll
        for (int k = 0; k < 16; k++) {
            ulonglong2 a = *(const ulonglong2*)(&sA[k][bg4]);
            float4 w = *(const float4*)(&sW[k][cg4]);
            ull w0 = pack2(w.x, w.x), w1 = pack2(w.y, w.y);
            ull w2 = pack2(w.z, w.z), w3 = pack2(w.w, w.w);
            fma2(acc[0][0], a.x, w0); fma2(acc[0][1], a.y, w0);
            fma2(acc[1][0], a.x, w1); fma2(acc[1][1], a.y, w1);
            fma2(acc[2][0], a.x, w2); fma2(acc[2][1], a.y, w2);
            fma2(acc[3][0], a.x, w3); fma2(acc[3][1], a.y, w3);
        }
    }
#pragma unroll
    for (int c = 0; c < 4; c++) {
        int col = cb + cg4 + c;
        if (col < OUTD) {
            float bv = bp[col];
            ull bpp = pack2(bv, bv);
            ulonglong2 v;
            v.x = add2(acc[c][0], bpp);
            v.y = add2(acc[c][1], bpp);
            *(ulonglong2*)(&g_dec[t][col][bg4]) = v;
        }
    }
}

__global__ void k_mdn(float* __restrict__ out) {
    int idx = blockIdx.x * blockDim.x + threadIdx.x;
    if (idx >= NSEQ * B * 21) return;
    int u = idx % 21;
    int r = idx / 21;
    int b = r & 63;
    int t = r >> 6;
    if (u < 20) {
        int m = u;
        int off = t * 20 * 64 + m * 64 + b;
        out[off] = 1.0f;
        out[163840 + off] = g_dec[t][6 * m + 1][b];
        out[327680 + off] = g_dec[t][6 * m + 2][b];
        out[491520 + off] = expf(g_dec[t][6 * m + 3][b]);
        out[655360 + off] = expf(g_dec[t][6 * m + 4][b]);
        out[819200 + off] = tanhf(g_dec[t][6 * m + 5][b]);
    } else {
        float p0 = g_dec[t][120][b], p1 = g_dec[t][121][b], p2 = g_dec[t][122][b];
        float mx = fmaxf(p0, fmaxf(p1, p2));
        float e0 = expf(p0 - mx), e1 = expf(p1 - mx), e2 = expf(p2 - mx);
        float s = e0 + e1 + e2;
        int base = 983040 + t * (B * 3) + b * 3;
        out[base + 0] = e0 / s;
        out[base + 1] = e1 / s;
        out[base + 2] = e2 / s;
    }
}

// ---------------- host driver ------------------------------------------------
extern "C" void kernel_launch(void* const* d_in, const int* in_sizes, int n_in,
                              void* d_out, int out_size) {
    const float* z        = (const float*)d_in[0];
    const float* strokes  = (const float*)d_in[1];
    const float* fc_in_w  = (const float*)d_in[2];
    const float* fc_in_b  = (const float*)d_in[3];
    const float* fc_proj_w= (const float*)d_in[4];
    const float* fc_proj_b= (const float*)d_in[5];
    const float* Wx       = (const float*)d_in[6];
    const float* Wh       = (const float*)d_in[7];
    const float* b0       = (const float*)d_in[8];
    const float* Wxh      = (const float*)d_in[9];
    const float* Whh      = (const float*)d_in[10];
    const float* bhy      = (const float*)d_in[11];
    const float* Wzx      = (const float*)d_in[12];
    const float* bzx      = (const float*)d_in[13];
    const float* Wzh      = (const float*)d_in[14];
    const float* bzh      = (const float*)d_in[15];
    const float* Wzb      = (const float*)d_in[16];
    const float* Dx       = (const float*)d_in[17];
    const float* Dh       = (const float*)d_in[18];
    const float* Db       = (const float*)d_in[19];
    float* out = (float*)d_out;

    k_transpose<<<(NSEQ * B * IND + 255) / 256, 256>>>(strokes);
    k_init<<<(B * 2560 + 255) / 256, 256>>>(z, fc_in_w, fc_in_b);
    k_pre_ax<<<dim3(64, NSEQ), 256>>>(Wx);
    k_pre_gxh<<<dim3(16, NSEQ), 256>>>(Wxh);

    k_seq<<<GRID, 256>>>(Wxh, Whh, bhy, Wh, Wzx, bzx, Wzh, bzh, Wzb,
                         b0, Dx, Dh, Db);

    dim3 pg(2, NSEQ);
    k_proj<<<pg, 256>>>(fc_proj_w, fc_proj_b);
    k_mdn<<<(NSEQ * B * 21 + 255) / 256, 256>>>(out);
}

// round 15
// speedup vs baseline: 1.1269x; 1.0727x over previous
#include <cuda_runtime.h>
#include <math.h>
#include <stdint.h>

typedef unsigned long long ull;

#define B 64
#define H 1024
#define HY 256
#define F 64
#define IND 133
#define NSEQ 128
#define OUTD 123
#define GRID 148

// ---------------- persistent device state ----------------------------------
__device__ __align__(16) float g_h[H][B];
__device__ __align__(16) float g_c[H][B];
__device__ __align__(16) float g_hh[2][HY][B];
__device__ __align__(16) float g_ch[HY][B];
__device__ __align__(16) float g_z[3 * HY][B];
__device__ __align__(16) float g_ahp[4][4 * H][B];      // h@Wh split-K partials
__device__ __align__(16) float g_x[NSEQ][IND][B];
__device__ __align__(16) float g_axp[NSEQ][4 * H][B];   // precomputed x@Wx
__device__ __align__(16) float g_gxh[NSEQ][4 * HY][B];  // precomputed x@Wxh(x-rows)
__device__ __align__(16) float g_outs[NSEQ][H][B];
__device__ __align__(16) float g_dec[NSEQ][OUTD][B];
__device__ unsigned g_bar_count;
__device__ unsigned g_bar_gen;

__device__ __forceinline__ float sigf(float x) { return 1.0f / (1.0f + expf(-x)); }

__device__ __forceinline__ void fma2(ull& d, ull a, ull b) {
    asm("fma.rn.f32x2 %0, %1, %2, %0;" : "+l"(d) : "l"(a), "l"(b));
}
__device__ __forceinline__ ull mul2(ull a, ull b) {
    ull d; asm("mul.rn.f32x2 %0, %1, %2;" : "=l"(d) : "l"(a), "l"(b)); return d;
}
__device__ __forceinline__ ull add2(ull a, ull b) {
    ull d; asm("add.rn.f32x2 %0, %1, %2;" : "=l"(d) : "l"(a), "l"(b)); return d;
}
__device__ __forceinline__ ull pack2(float x, float y) {
    ull r; asm("mov.b64 %0, {%1, %2};" : "=l"(r) : "f"(x), "f"(y)); return r;
}

// ---------------- cp.async helpers ------------------------------------------
__device__ __forceinline__ void cpa16(void* dst, const void* src) {
    unsigned d = (unsigned)__cvta_generic_to_shared(dst);
    asm volatile("cp.async.cg.shared.global [%0], [%1], 16;" :: "r"(d), "l"(src));
}
__device__ __forceinline__ void cpa_commit() {
    asm volatile("cp.async.commit_group;");
}
template<int N>
__device__ __forceinline__ void cpa_wait() {
    asm volatile("cp.async.wait_group %0;" :: "n"(N));
}

// ---------------- grid-wide barrier (R9 proven version) ----------------------
__device__ __forceinline__ void grid_bar() {
    __syncthreads();
    if (threadIdx.x == 0) {
        unsigned gen = *(volatile unsigned*)&g_bar_gen;
        __threadfence();
        unsigned arr = atomicAdd(&g_bar_count, 1u);
        if (arr == GRID - 1) {
            *(volatile unsigned*)&g_bar_count = 0u;
            __threadfence();
            *(volatile unsigned*)&g_bar_gen = gen + 1u;
        } else {
            while (*(volatile unsigned*)&g_bar_gen == gen) {}
        }
        __threadfence();
    }
    __syncthreads();
}

// ---------------- double-buffered 32-col GEMM core (R9 proven) ---------------
// acc[4] (+=): cols cb..cb+31 (thread: cols cg4..cg4+3 where cg4=(tid>>5)<<2,
// batch pair bg2=(tid&31)<<1), K = 32*nst over A[k][64].
// GATHER: W cols are 4 gate-strided groups of 8 (cb = jbase).
// smem: sA = sm[0..4096), sW = sm[4096..6144).
template<bool GATHER>
__device__ __forceinline__ void mm32(const float* __restrict__ A,
                                     const float* __restrict__ W,
                                     int ldw, int cb, int nst,
                                     float* sm, ull (&acc)[4], int tid) {
    float* sA = sm;
    float* sW = sm + 4096;
    const int ar  = tid >> 4;
    const int ac4 = (tid & 15) << 2;
    const int wr  = tid >> 3;
    const int wq  = tid & 7;
    const int cg4 = (tid >> 5) << 2;
    const int bg2 = (tid & 31) << 1;

    // stage 0 loads
    {
        cpa16(sA + ar * 64 + ac4, A + ar * 64 + ac4);
        cpa16(sA + (ar + 16) * 64 + ac4, A + (ar + 16) * 64 + ac4);
        const float* ws = GATHER
            ? (W + wr * ldw + ((wq >> 1) << 8) + cb + ((wq & 1) << 2))
            : (W + wr * ldw + cb + (wq << 2));
        cpa16(sW + wr * 32 + (wq << 2), ws);
        cpa_commit();
    }
    for (int s = 0; s < nst; s++) {
        int buf = s & 1;
        if (s + 1 < nst) {
            int k0 = (s + 1) << 5;
            float* dA = sA + (buf ^ 1) * 2048;
            float* dW = sW + (buf ^ 1) * 1024;
            cpa16(dA + ar * 64 + ac4, A + (k0 + ar) * 64 + ac4);
            cpa16(dA + (ar + 16) * 64 + ac4, A + (k0 + ar + 16) * 64 + ac4);
            const float* ws = GATHER
                ? (W + (k0 + wr) * ldw + ((wq >> 1) << 8) + cb + ((wq & 1) << 2))
                : (W + (k0 + wr) * ldw + cb + (wq << 2));
            cpa16(dW + wr * 32 + (wq << 2), ws);
            cpa_commit();
            cpa_wait<1>();
        } else {
            cpa_wait<0>();
        }
        __syncthreads();
        const float* cA = sA + buf * 2048;
        const float* cW = sW + buf * 1024;
#pragma unroll
        for (int k = 0; k < 32; k++) {
            ull a = *(const ull*)(cA + k * 64 + bg2);
            float4 w = *(const float4*)(cW + k * 32 + cg4);
            fma2(acc[0], a, pack2(w.x, w.x));
            fma2(acc[1], a, pack2(w.y, w.y));
            fma2(acc[2], a, pack2(w.z, w.z));
            fma2(acc[3], a, pack2(w.w, w.w));
        }
        __syncthreads();
    }
}

// ---------------- prologue kernels ------------------------------------------
__global__ void k_transpose(const float* __restrict__ strokes) {
    int idx = blockIdx.x * blockDim.x + threadIdx.x;
    if (idx >= NSEQ * B * IND) return;
    int t = idx / (B * IND);
    int r = idx - t * (B * IND);
    int b = r / IND;
    int k = r - b * IND;
    g_x[t][k][b] = strokes[idx];
}

__global__ void k_init(const float* __restrict__ z, const float* __restrict__ w,
                       const float* __restrict__ bias) {
    int idx = blockIdx.x * blockDim.x + threadIdx.x;
    int b = idx & 63;
    int col = idx >> 6;
    if (col >= 2560) return;
    float acc = bias[col];
#pragma unroll 4
    for (int k = 0; k < 128; k++) acc += z[b * 128 + k] * w[k * 2560 + col];
    float v = tanhf(acc);
    if (col < 1024)       g_h[col][b] = v;
    else if (col < 2048)  g_c[col - 1024][b] = v;
    else if (col < 2304)  g_hh[0][col - 2048][b] = v;
    else                  g_ch[col - 2304][b] = v;
}

// Big-tile x-projection: 256 cols x 64 batch per block, 8c x 8b register tile,
// cp.async double-buffered. which=0 -> g_axp (Wx, ldw 4096); which=1 -> g_gxh
// (Wxh x-rows, ldw 1024). Destination resolved DEVICE-side (symbol address).
__global__ void __launch_bounds__(256, 2) k_pre2(const float* __restrict__ W,
                                                 int ldw, int which) {
    __shared__ __align__(16) float sA[2][1024];    // 16k x 64b
    __shared__ __align__(16) float sW[2][4096];    // 16k x 256c
    const int t = blockIdx.y;
    const int cb = blockIdx.x * 256;
    const int tid = threadIdx.x;
    const float* A = &g_x[t][0][0];
    const int bg8 = (tid & 7) << 3;
    const int cg8 = (tid >> 3) << 3;
    const int NST = (IND + 15) >> 4;  // 9

    auto load = [&](int s) {
        int k0 = s << 4;
        int kt = IND - k0; if (kt > 16) kt = 16;
        int buf = s & 1;
        {
            int row = tid >> 4, b4 = (tid & 15) << 2;
            if (row < kt) cpa16(&sA[buf][row * 64 + b4], A + (k0 + row) * 64 + b4);
        }
#pragma unroll
        for (int p = 0; p < 4; p++) {
            int i = tid + (p << 8);
            int row = i >> 6, c4 = (i & 63) << 2;
            if (row < kt) cpa16(&sW[buf][row * 256 + c4], W + (k0 + row) * ldw + cb + c4);
        }
        cpa_commit();
    };

    load(0);
    ull acc[8][4] = {};
    for (int s = 0; s < NST; s++) {
        if (s + 1 < NST) { load(s + 1); cpa_wait<1>(); } else { cpa_wait<0>(); }
        __syncthreads();
        int k0 = s << 4;
        int kt = IND - k0; if (kt > 16) kt = 16;
        const float* cA = sA[s & 1];
        const float* cW = sW[s & 1];
#define PRE2_BODY(k) do {                                                      \
            ulonglong2 a01 = *(const ulonglong2*)(cA + (k) * 64 + bg8);        \
            ulonglong2 a23 = *(const ulonglong2*)(cA + (k) * 64 + bg8 + 4);    \
            float4 w0 = *(const float4*)(cW + (k) * 256 + cg8);                \
            float4 w1 = *(const float4*)(cW + (k) * 256 + cg8 + 4);            \
            ull wp;                                                            \
            wp = pack2(w0.x, w0.x);                                            \
            fma2(acc[0][0], a01.x, wp); fma2(acc[0][1], a01.y, wp);            \
            fma2(acc[0][2], a23.x, wp); fma2(acc[0][3], a23.y, wp);            \
            wp = pack2(w0.y, w0.y);                                            \
            fma2(acc[1][0], a01.x, wp); fma2(acc[1][1], a01.y, wp);            \
            fma2(acc[1][2], a23.x, wp); fma2(acc[1][3], a23.y, wp);            \
            wp = pack2(w0.z, w0.z);                                            \
            fma2(acc[2][0], a01.x, wp); fma2(acc[2][1], a01.y, wp);            \
            fma2(acc[2][2], a23.x, wp); fma2(acc[2][3], a23.y, wp);            \
            wp = pack2(w0.w, w0.w);                                            \
            fma2(acc[3][0], a01.x, wp); fma2(acc[3][1], a01.y, wp);            \
            fma2(acc[3][2], a23.x, wp); fma2(acc[3][3], a23.y, wp);            \
            wp = pack2(w1.x, w1.x);                                            \
            fma2(acc[4][0], a01.x, wp); fma2(acc[4][1], a01.y, wp);            \
            fma2(acc[4][2], a23.x, wp); fma2(acc[4][3], a23.y, wp);            \
            wp = pack2(w1.y, w1.y);                                            \
            fma2(acc[5][0], a01.x, wp); fma2(acc[5][1], a01.y, wp);            \
            fma2(acc[5][2], a23.x, wp); fma2(acc[5][3], a23.y, wp);            \
            wp = pack2(w1.z, w1.z);                                            \
            fma2(acc[6][0], a01.x, wp); fma2(acc[6][1], a01.y, wp);            \
            fma2(acc[6][2], a23.x, wp); fma2(acc[6][3], a23.y, wp);            \
            wp = pack2(w1.w, w1.w);                                            \
            fma2(acc[7][0], a01.x, wp); fma2(acc[7][1], a01.y, wp);            \
            fma2(acc[7][2], a23.x, wp); fma2(acc[7][3], a23.y, wp);            \
        } while (0)
        if (kt == 16) {
#pragma unroll
            for (int k = 0; k < 16; k++) PRE2_BODY(k);
        } else {
            for (int k = 0; k < kt; k++) PRE2_BODY(k);
        }
#undef PRE2_BODY
        __syncthreads();
    }

    float* outT = (which == 0) ? &g_axp[t][0][0] : &g_gxh[t][0][0];
#pragma unroll
    for (int c = 0; c < 8; c++) {
        int col = cb + cg8 + c;
        ulonglong2 v0; v0.x = acc[c][0]; v0.y = acc[c][1];
        ulonglong2 v1; v1.x = acc[c][2]; v1.y = acc[c][3];
        *(ulonglong2*)(outT + col * 64 + bg8) = v0;
        *(ulonglong2*)(outT + col * 64 + bg8 + 4) = v1;
    }
}

// ---------------- THE persistent recurrence kernel (R9 + phase-C prefetch) ---
__global__ void __launch_bounds__(256, 1) k_seq(
        const float* __restrict__ Wxh, const float* __restrict__ Whh,
        const float* __restrict__ bhy, const float* __restrict__ Wh,
        const float* __restrict__ Wzx, const float* __restrict__ bzx,
        const float* __restrict__ Wzh, const float* __restrict__ bzh,
        const float* __restrict__ Wzb, const float* __restrict__ b0,
        const float* __restrict__ Dx, const float* __restrict__ Dh,
        const float* __restrict__ Db) {
    // union: phase A/B use [0,6144) for mm32; phase C uses
    // sZ [0,6144), sWD [6144,7680), sPre [7680,11776)  -> 47KB
    __shared__ __align__(16) float sm[11776];
    const int bx = blockIdx.x;
    const int tid = threadIdx.x;
    const float* WxhH = Wxh + IND * 1024;

    const int cg4 = (tid >> 5) << 2;
    const int bg2 = (tid & 31) << 1;

    for (int t = 0; t < NSEQ; t++) {
        const int cur = t & 1, nxt = cur ^ 1;

        // ================= phase A: hyper (32 blocks) || h@Wh (116 blocks) ===
        if (bx < 32) {
            const int jbase = bx * 8;
            ull acc[4];
#pragma unroll
            for (int i = 0; i < 4; i++) {
                int c = cg4 + i;
                acc[i] = *(const ull*)(&g_gxh[t][((c >> 3) << 8) + jbase + (c & 7)][bg2]);
            }
            mm32<true>(&g_h[0][0],       WxhH, 1024, jbase, 32, sm, acc, tid);
            mm32<true>(&g_hh[cur][0][0], Whh,  1024, jbase, 8,  sm, acc, tid);

            float* sPre = sm;  // 2048 floats (free after mm32)
#pragma unroll
            for (int i = 0; i < 4; i++) {
                int c = cg4 + i;
                float bv = bhy[((c >> 3) << 8) + jbase + (c & 7)];
                *(ull*)(&sPre[c * 64 + bg2]) = add2(acc[i], pack2(bv, bv));
            }
            __syncthreads();
#pragma unroll
            for (int r = 0; r < 2; r++) {
                int idx = tid + (r << 8);
                int jl = idx >> 6, b = idx & 63;
                int jg = jbase + jl;
                float iv = sPre[jl * 64 + b];
                float fv = sPre[(8 + jl) * 64 + b];
                float gv = sPre[(16 + jl) * 64 + b];
                float ov = sPre[(24 + jl) * 64 + b];
                float chv = sigf(fv) * g_ch[jg][b] + sigf(iv) * tanhf(gv);
                g_ch[jg][b] = chv;
                g_hh[nxt][jg][b] = sigf(ov) * tanhf(chv);
            }
        } else {
            // h @ Wh : 512 units of (32 cols, K=256). 48 blocks x5, 68 blocks x4.
            int w0 = bx - 32;
            int start = (w0 < 48) ? w0 * 5 : 240 + (w0 - 48) * 4;
            int cnt = (w0 < 48) ? 5 : 4;
            for (int i = 0; i < cnt; i++) {
                int u = start + i;
                int ct = u >> 2, ks = u & 3;
                ull acc[4] = {};
                mm32<false>(&g_h[ks * 256][0], Wh + ks * 256 * 4096, 4096,
                            ct * 32, 8, sm, acc, tid);
#pragma unroll
                for (int c = 0; c < 4; c++)
                    *(ull*)(&g_ahp[ks][ct * 32 + cg4 + c][bg2]) = acc[c];
            }
        }
        grid_bar();

        // ================= phase B: z projections (24 blocks) ================
        if (bx < 24) {
            int type = bx >> 3, cb = (bx & 7) * 32;
            const float* W = (type == 0) ? Wzx : (type == 1) ? Wzh : Wzb;
            ull acc[4] = {};
            mm32<false>(&g_hh[nxt][0][0], W, 256, cb, 8, sm, acc, tid);
#pragma unroll
            for (int c = 0; c < 4; c++) {
                int col = cb + cg4 + c;
                float bv = (type == 0) ? bzx[col] : (type == 1) ? bzh[col] : 0.0f;
                *(ull*)(&g_z[type * 256 + col][bg2]) = add2(acc[c], pack2(bv, bv));
            }
        }
        grid_bar();

        // ================= phase C: einsums + combine + cell (64 blocks) =====
        if (bx < 64) {
            const int jt = bx;
            const int bg4 = (tid & 15) << 2;
            const int cg16 = tid >> 4;          // 0..15 -> 4 local cols
            const int gate = cg16 >> 2;
            const int j4 = (cg16 & 3) << 2;

            ull sx[4][2] = {}, sh[4][2] = {}, sb[4][2] = {};

            // stage loader: f-chunk of 4; sZ[ty][g][fr][64]  sWD[ty][fr][64]
            {
                int f0 = 0;
#pragma unroll
                for (int p = 0; p < 3; p++) {
                    int i = tid + (p << 8);
                    int b4 = (i & 15) << 2;
                    int r = i >> 4;
                    int fr = r & 3, g = (r >> 2) & 3, ty = r >> 4;
                    cpa16(sm + ((ty * 4 + g) * 4 + fr) * 64 + b4,
                          &g_z[ty * 256 + g * 64 + f0 + fr][b4]);
                }
                if (tid < 192) {
                    int ty = tid >> 6, rem = tid & 63;
                    int fr = rem >> 4, c4 = (rem & 15) << 2;
                    const float* D = (ty == 0) ? Dx : (ty == 1) ? Dh : Db;
                    cpa16(sm + 6144 + (ty * 4 + fr) * 64 + c4,
                          D + ((c4 >> 4) * 64 + f0 + fr) * 1024 + jt * 16 + (c4 & 15));
                }
                cpa_commit();
            }

            // prefetch combine inputs: these LDGs stay in flight across the
            // whole 16-stage einsum loop (ptxas won't sink loads across BARs).
            ulonglong2 pax[4], pA0[4], pA1[4], pA2[4], pA3[4];
            float pb[4];
#pragma unroll
            for (int c = 0; c < 4; c++) {
                int col = gate * 1024 + jt * 16 + j4 + c;
                pax[c] = *(const ulonglong2*)(&g_axp[t][col][bg4]);
                pA0[c] = *(const ulonglong2*)(&g_ahp[0][col][bg4]);
                pA1[c] = *(const ulonglong2*)(&g_ahp[1][col][bg4]);
                pA2[c] = *(const ulonglong2*)(&g_ahp[2][col][bg4]);
                pA3[c] = *(const ulonglong2*)(&g_ahp[3][col][bg4]);
                pb[c] = b0[col];
            }

            for (int st = 0; st < 16; st++) {
                int buf = st & 1;
                if (st + 1 < 16) {
                    int f0 = (st + 1) << 2;
                    float* dZ = sm + (buf ^ 1) * 3072;
                    float* dW = sm + 6144 + (buf ^ 1) * 768;
#pragma unroll
                    for (int p = 0; p < 3; p++) {
                        int i = tid + (p << 8);
                        int b4 = (i & 15) << 2;
                        int r = i >> 4;
                        int fr = r & 3, g = (r >> 2) & 3, ty = r >> 4;
                        cpa16(dZ + ((ty * 4 + g) * 4 + fr) * 64 + b4,
                              &g_z[ty * 256 + g * 64 + f0 + fr][b4]);
                    }
                    if (tid < 192) {
                        int ty = tid >> 6, rem = tid & 63;
                        int fr = rem >> 4, c4 = (rem & 15) << 2;
                        const float* D = (ty == 0) ? Dx : (ty == 1) ? Dh : Db;
                        cpa16(dW + (ty * 4 + fr) * 64 + c4,
                              D + ((c4 >> 4) * 64 + f0 + fr) * 1024 + jt * 16 + (c4 & 15));
                    }
                    cpa_commit();
                    cpa_wait<1>();
                } else {
                    cpa_wait<0>();
                }
                __syncthreads();
                const float* cZ = sm + buf * 3072;
                const float* cW = sm + 6144 + buf * 768;
#pragma unroll
                for (int k = 0; k < 4; k++) {
                    ulonglong2 azx = *(const ulonglong2*)(cZ + ((0 * 4 + gate) * 4 + k) * 64 + bg4);
                    ulonglong2 azh = *(const ulonglong2*)(cZ + ((1 * 4 + gate) * 4 + k) * 64 + bg4);
                    ulonglong2 azb = *(const ulonglong2*)(cZ + ((2 * 4 + gate) * 4 + k) * 64 + bg4);
                    float4 wx = *(const float4*)(cW + (0 * 4 + k) * 64 + cg16 * 4);
                    float4 wh = *(const float4*)(cW + (1 * 4 + k) * 64 + cg16 * 4);
                    float4 wb = *(const float4*)(cW + (2 * 4 + k) * 64 + cg16 * 4);
#pragma unroll
                    for (int c = 0; c < 4; c++) {
                        float wxc = (c == 0) ? wx.x : (c == 1) ? wx.y : (c == 2) ? wx.z : wx.w;
                        float whc = (c == 0) ? wh.x : (c == 1) ? wh.y : (c == 2) ? wh.z : wh.w;
                        float wbc = (c == 0) ? wb.x : (c == 1) ? wb.y : (c == 2) ? wb.z : wb.w;
                        ull wxp = pack2(wxc, wxc), whp = pack2(whc, whc), wbp = pack2(wbc, wbc);
                        fma2(sx[c][0], azx.x, wxp); fma2(sx[c][1], azx.y, wxp);
                        fma2(sh[c][0], azh.x, whp); fma2(sh[c][1], azh.y, whp);
                        fma2(sb[c][0], azb.x, wbp); fma2(sb[c][1], azb.y, wbp);
                    }
                }
                __syncthreads();
            }

            float* sPre = sm + 7680;  // 4096 floats: [64 cols][64 batch]
#pragma unroll
            for (int c = 0; c < 4; c++) {
                ull ahx = add2(add2(pA0[c].x, pA1[c].x), add2(pA2[c].x, pA3[c].x));
                ull ahy = add2(add2(pA0[c].y, pA1[c].y), add2(pA2[c].y, pA3[c].y));
                ull bp = pack2(pb[c], pb[c]);
                ull p0 = mul2(sx[c][0], pax[c].x); fma2(p0, sh[c][0], ahx);
                p0 = add2(p0, sb[c][0]); p0 = add2(p0, bp);
                ull p1 = mul2(sx[c][1], pax[c].y); fma2(p1, sh[c][1], ahy);
                p1 = add2(p1, sb[c][1]); p1 = add2(p1, bp);
                *(ull*)(&sPre[(gate * 16 + j4 + c) * 64 + bg4]) = p0;
                *(ull*)(&sPre[(gate * 16 + j4 + c) * 64 + bg4 + 2]) = p1;
            }
            __syncthreads();

#pragma unroll
            for (int r = 0; r < 4; r++) {
                int idx = tid + (r << 8);
                int jl = idx >> 6, b = idx & 63;
                int jg = jt * 16 + jl;
                float iv = sPre[(0 * 16 + jl) * 64 + b];
                float fv = sPre[(1 * 16 + jl) * 64 + b];
                float gv = sPre[(2 * 16 + jl) * 64 + b];
                float ov = sPre[(3 * 16 + jl) * 64 + b];
                float cv = sigf(fv) * g_c[jg][b] + sigf(iv) * tanhf(gv);
                g_c[jg][b] = cv;
                float hn = sigf(ov) * tanhf(cv);
                g_h[jg][b] = hn;
                g_outs[t][jg][b] = hn;
            }
        }
        grid_bar();
    }
}

// ---------------- epilogue ---------------------------------------------------
__global__ void __launch_bounds__(256) k_proj(const float* __restrict__ Wp,
                                              const float* __restrict__ bp) {
    __shared__ __align__(16) float smem[2048];
    float (*sA)[64] = (float(*)[64])smem;
    float (*sW)[64] = (float(*)[64])(smem + 1024);
    int t = blockIdx.y;
    int cb = blockIdx.x * 64;
    int tid = threadIdx.x;
    const float* A = &g_outs[t][0][0];
    const int row = tid >> 4;
    const int q4 = (tid & 15) << 2;
    const int bg4 = (tid & 15) << 2;
    const int cg4 = (tid >> 4) << 2;
    ull acc[4][2] = {};

    float4 pa = *(const float4*)(A + row * 64 + q4);
    float4 pw;
    {
        const float* wr = Wp + row * OUTD + cb + q4;
        pw.x = (cb + q4 + 0 < OUTD) ? wr[0] : 0.f;
        pw.y = (cb + q4 + 1 < OUTD) ? wr[1] : 0.f;
        pw.z = (cb + q4 + 2 < OUTD) ? wr[2] : 0.f;
        pw.w = (cb + q4 + 3 < OUTD) ? wr[3] : 0.f;
    }
    for (int s = 0; s < 64; s++) {
        __syncthreads();
        *(float4*)(&sA[row][q4]) = pa;
        *(float4*)(&sW[row][q4]) = pw;
        __syncthreads();
        if (s + 1 < 64) {
            int kn = (s + 1) * 16 + row;
            pa = *(const float4*)(A + kn * 64 + q4);
            const float* wr = Wp + kn * OUTD + cb + q4;
            pw.x = (cb + q4 + 0 < OUTD) ? wr[0] : 0.f;
            pw.y = (cb + q4 + 1 < OUTD) ? wr[1] : 0.f;
            pw.z = (cb + q4 + 2 < OUTD) ? wr[2] : 0.f;
            pw.w = (cb + q4 + 3 < OUTD) ? wr[3] : 0.f;
        }
#pragma unroll
        for (int k = 0; k < 16; k++) {
            ulonglong2 a = *(const ulonglong2*)(&sA[k][bg4]);
            float4 w = *(const float4*)(&sW[k][cg4]);
            ull w0 = pack2(w.x, w.x), w1 = pack2(w.y, w.y);
            ull w2 = pack2(w.z, w.z), w3 = pack2(w.w, w.w);
            fma2(acc[0][0], a.x, w0); fma2(acc[0][1], a.y, w0);
            fma2(acc[1][0], a.x, w1); fma2(acc[1][1], a.y, w1);
            fma2(acc[2][0], a.x, w2); fma2(acc[2][1], a.y, w2);
            fma2(acc[3][0], a.x, w3); fma2(acc[3][1], a.y, w3);
        }
    }
#pragma unroll
    for (int c = 0; c < 4; c++) {
        int col = cb + cg4 + c;
        if (col < OUTD) {
            float bv = bp[col];
            ull bpp = pack2(bv, bv);
            ulonglong2 v;
            v.x = add2(acc[c][0], bpp);
            v.y = add2(acc[c][1], bpp);
            *(ulonglong2*)(&g_dec[t][col][bg4]) = v;
        }
    }
}

__global__ void k_mdn(float* __restrict__ out) {
    int idx = blockIdx.x * blockDim.x + threadIdx.x;
    if (idx >= NSEQ * B * 21) return;
    int u = idx % 21;
    int r = idx / 21;
    int b = r & 63;
    int t = r >> 6;
    if (u < 20) {
        int m = u;
        int off = t * 20 * 64 + m * 64 + b;
        out[off] = 1.0f;
        out[163840 + off] = g_dec[t][6 * m + 1][b];
        out[327680 + off] = g_dec[t][6 * m + 2][b];
        out[491520 + off] = expf(g_dec[t][6 * m + 3][b]);
        out[655360 + off] = expf(g_dec[t][6 * m + 4][b]);
        out[819200 + off] = tanhf(g_dec[t][6 * m + 5][b]);
    } else {
        float p0 = g_dec[t][120][b], p1 = g_dec[t][121][b], p2 = g_dec[t][122][b];
        float mx = fmaxf(p0, fmaxf(p1, p2));
        float e0 = expf(p0 - mx), e1 = expf(p1 - mx), e2 = expf(p2 - mx);
        float s = e0 + e1 + e2;
        int base = 983040 + t * (B * 3) + b * 3;
        out[base + 0] = e0 / s;
        out[base + 1] = e1 / s;
        out[base + 2] = e2 / s;
    }
}

// ---------------- host driver ------------------------------------------------
extern "C" void kernel_launch(void* const* d_in, const int* in_sizes, int n_in,
                              void* d_out, int out_size) {
    const float* z        = (const float*)d_in[0];
    const float* strokes  = (const float*)d_in[1];
    const float* fc_in_w  = (const float*)d_in[2];
    const float* fc_in_b  = (const float*)d_in[3];
    const float* fc_proj_w= (const float*)d_in[4];
    const float* fc_proj_b= (const float*)d_in[5];
    const float* Wx       = (const float*)d_in[6];
    const float* Wh       = (const float*)d_in[7];
    const float* b0       = (const float*)d_in[8];
    const float* Wxh      = (const float*)d_in[9];
    const float* Whh      = (const float*)d_in[10];
    const float* bhy      = (const float*)d_in[11];
    const float* Wzx      = (const float*)d_in[12];
    const float* bzx      = (const float*)d_in[13];
    const float* Wzh      = (const float*)d_in[14];
    const float* bzh      = (const float*)d_in[15];
    const float* Wzb      = (const float*)d_in[16];
    const float* Dx       = (const float*)d_in[17];
    const float* Dh       = (const float*)d_in[18];
    const float* Db       = (const float*)d_in[19];
    float* out = (float*)d_out;

    k_transpose<<<(NSEQ * B * IND + 255) / 256, 256>>>(strokes);
    k_init<<<(B * 2560 + 255) / 256, 256>>>(z, fc_in_w, fc_in_b);
    // x @ Wx : 4096 cols -> 16 ctiles ; x @ Wxh(x-rows) : 1024 cols -> 4 ctiles
    k_pre2<<<dim3(16, NSEQ), 256>>>(Wx, 4096, 0);
    k_pre2<<<dim3(4, NSEQ), 256>>>(Wxh, 1024, 1);

    k_seq<<<GRID, 256>>>(Wxh, Whh, bhy, Wh, Wzx, bzx, Wzh, bzh, Wzb,
                         b0, Dx, Dh, Db);

    dim3 pg(2, NSEQ);
    k_proj<<<pg, 256>>>(fc_proj_w, fc_proj_b);
    k_mdn<<<(NSEQ * B * 21 + 255) / 256, 256>>>(out);
}

// round 16
// speedup vs baseline: 1.1814x; 1.0484x over previous
#include <cuda_runtime.h>
#include <math.h>
#include <stdint.h>

typedef unsigned long long ull;

#define B 64
#define H 1024
#define HY 256
#define F 64
#define IND 133
#define NSEQ 128
#define OUTD 123
#define GRID 148

// ---------------- persistent device state ----------------------------------
__device__ __align__(16) float g_h[H][B];
__device__ __align__(16) float g_c[H][B];
__device__ __align__(16) float g_hh[2][HY][B];
__device__ __align__(16) float g_ch[HY][B];
__device__ __align__(16) float g_z[3 * HY][B];
__device__ __align__(16) float g_ahp[4][4 * H][B];      // h@Wh split-K partials
__device__ __align__(16) float g_x[NSEQ][IND][B];
__device__ __align__(16) float g_axp[NSEQ][4 * H][B];   // precomputed x@Wx
__device__ __align__(16) float g_gxh[NSEQ][4 * HY][B];  // precomputed x@Wxh(x-rows)
__device__ __align__(16) float g_outs[NSEQ][H][B];
__device__ __align__(16) float g_dec[NSEQ][OUTD][B];
__device__ unsigned g_bar_count;
__device__ unsigned g_bar_gen;

__device__ __forceinline__ float sigf(float x) { return 1.0f / (1.0f + expf(-x)); }

__device__ __forceinline__ void fma2(ull& d, ull a, ull b) {
    asm("fma.rn.f32x2 %0, %1, %2, %0;" : "+l"(d) : "l"(a), "l"(b));
}
__device__ __forceinline__ ull mul2(ull a, ull b) {
    ull d; asm("mul.rn.f32x2 %0, %1, %2;" : "=l"(d) : "l"(a), "l"(b)); return d;
}
__device__ __forceinline__ ull add2(ull a, ull b) {
    ull d; asm("add.rn.f32x2 %0, %1, %2;" : "=l"(d) : "l"(a), "l"(b)); return d;
}
__device__ __forceinline__ ull pack2(float x, float y) {
    ull r; asm("mov.b64 %0, {%1, %2};" : "=l"(r) : "f"(x), "f"(y)); return r;
}

// ---------------- cp.async helpers ------------------------------------------
__device__ __forceinline__ void cpa16(void* dst, const void* src) {
    unsigned d = (unsigned)__cvta_generic_to_shared(dst);
    asm volatile("cp.async.cg.shared.global [%0], [%1], 16;" :: "r"(d), "l"(src));
}
__device__ __forceinline__ void cpa_commit() {
    asm volatile("cp.async.commit_group;");
}
template<int N>
__device__ __forceinline__ void cpa_wait() {
    asm volatile("cp.async.wait_group %0;" :: "n"(N));
}

// ---------------- grid-wide barrier (R9 proven version) ----------------------
__device__ __forceinline__ void grid_bar() {
    __syncthreads();
    if (threadIdx.x == 0) {
        unsigned gen = *(volatile unsigned*)&g_bar_gen;
        __threadfence();
        unsigned arr = atomicAdd(&g_bar_count, 1u);
        if (arr == GRID - 1) {
            *(volatile unsigned*)&g_bar_count = 0u;
            __threadfence();
            *(volatile unsigned*)&g_bar_gen = gen + 1u;
        } else {
            while (*(volatile unsigned*)&g_bar_gen == gen) {}
        }
        __threadfence();
    }
    __syncthreads();
}

// ---------------- double-buffered 32-col GEMM core (R9 proven) ---------------
// acc[4] (+=): cols cb..cb+31 (thread: cols cg4..cg4+3 where cg4=(tid>>5)<<2,
// batch pair bg2=(tid&31)<<1), K = 32*nst over A[k][64].
// GATHER: W cols are 4 gate-strided groups of 8 (cb = jbase).
// smem: sA = sm[0..4096), sW = sm[4096..6144).
template<bool GATHER>
__device__ __forceinline__ void mm32(const float* __restrict__ A,
                                     const float* __restrict__ W,
                                     int ldw, int cb, int nst,
                                     float* sm, ull (&acc)[4], int tid) {
    float* sA = sm;
    float* sW = sm + 4096;
    const int ar  = tid >> 4;
    const int ac4 = (tid & 15) << 2;
    const int wr  = tid >> 3;
    const int wq  = tid & 7;
    const int cg4 = (tid >> 5) << 2;
    const int bg2 = (tid & 31) << 1;

    // stage 0 loads
    {
        cpa16(sA + ar * 64 + ac4, A + ar * 64 + ac4);
        cpa16(sA + (ar + 16) * 64 + ac4, A + (ar + 16) * 64 + ac4);
        const float* ws = GATHER
            ? (W + wr * ldw + ((wq >> 1) << 8) + cb + ((wq & 1) << 2))
            : (W + wr * ldw + cb + (wq << 2));
        cpa16(sW + wr * 32 + (wq << 2), ws);
        cpa_commit();
    }
    for (int s = 0; s < nst; s++) {
        int buf = s & 1;
        if (s + 1 < nst) {
            int k0 = (s + 1) << 5;
            float* dA = sA + (buf ^ 1) * 2048;
            float* dW = sW + (buf ^ 1) * 1024;
            cpa16(dA + ar * 64 + ac4, A + (k0 + ar) * 64 + ac4);
            cpa16(dA + (ar + 16) * 64 + ac4, A + (k0 + ar + 16) * 64 + ac4);
            const float* ws = GATHER
                ? (W + (k0 + wr) * ldw + ((wq >> 1) << 8) + cb + ((wq & 1) << 2))
                : (W + (k0 + wr) * ldw + cb + (wq << 2));
            cpa16(dW + wr * 32 + (wq << 2), ws);
            cpa_commit();
            cpa_wait<1>();
        } else {
            cpa_wait<0>();
        }
        __syncthreads();
        const float* cA = sA + buf * 2048;
        const float* cW = sW + buf * 1024;
#pragma unroll
        for (int k = 0; k < 32; k++) {
            ull a = *(const ull*)(cA + k * 64 + bg2);
            float4 w = *(const float4*)(cW + k * 32 + cg4);
            fma2(acc[0], a, pack2(w.x, w.x));
            fma2(acc[1], a, pack2(w.y, w.y));
            fma2(acc[2], a, pack2(w.z, w.z));
            fma2(acc[3], a, pack2(w.w, w.w));
        }
        __syncthreads();
    }
}

// ---------------- prologue kernels ------------------------------------------
__global__ void k_transpose(const float* __restrict__ strokes) {
    int idx = blockIdx.x * blockDim.x + threadIdx.x;
    if (idx >= NSEQ * B * IND) return;
    int t = idx / (B * IND);
    int r = idx - t * (B * IND);
    int b = r / IND;
    int k = r - b * IND;
    g_x[t][k][b] = strokes[idx];
}

__global__ void k_init(const float* __restrict__ z, const float* __restrict__ w,
                       const float* __restrict__ bias) {
    int idx = blockIdx.x * blockDim.x + threadIdx.x;
    int b = idx & 63;
    int col = idx >> 6;
    if (col >= 2560) return;
    float acc = bias[col];
#pragma unroll 4
    for (int k = 0; k < 128; k++) acc += z[b * 128 + k] * w[k * 2560 + col];
    float v = tanhf(acc);
    if (col < 1024)       g_h[col][b] = v;
    else if (col < 2048)  g_c[col - 1024][b] = v;
    else if (col < 2304)  g_hh[0][col - 2048][b] = v;
    else                  g_ch[col - 2304][b] = v;
}

// Big-tile x-projection: 256 cols x 64 batch per block, 8c x 8b register tile,
// cp.async double-buffered. which=0 -> g_axp (Wx, ldw 4096); which=1 -> g_gxh
// (Wxh x-rows, ldw 1024). Destination resolved DEVICE-side.
__global__ void __launch_bounds__(256, 2) k_pre2(const float* __restrict__ W,
                                                 int ldw, int which) {
    __shared__ __align__(16) float sA[2][1024];    // 16k x 64b
    __shared__ __align__(16) float sW[2][4096];    // 16k x 256c
    const int t = blockIdx.y;
    const int cb = blockIdx.x * 256;
    const int tid = threadIdx.x;
    const float* A = &g_x[t][0][0];
    const int bg8 = (tid & 7) << 3;
    const int cg8 = (tid >> 3) << 3;
    const int NST = (IND + 15) >> 4;  // 9

    auto load = [&](int s) {
        int k0 = s << 4;
        int kt = IND - k0; if (kt > 16) kt = 16;
        int buf = s & 1;
        {
            int row = tid >> 4, b4 = (tid & 15) << 2;
            if (row < kt) cpa16(&sA[buf][row * 64 + b4], A + (k0 + row) * 64 + b4);
        }
#pragma unroll
        for (int p = 0; p < 4; p++) {
            int i = tid + (p << 8);
            int row = i >> 6, c4 = (i & 63) << 2;
            if (row < kt) cpa16(&sW[buf][row * 256 + c4], W + (k0 + row) * ldw + cb + c4);
        }
        cpa_commit();
    };

    load(0);
    ull acc[8][4] = {};
    for (int s = 0; s < NST; s++) {
        if (s + 1 < NST) { load(s + 1); cpa_wait<1>(); } else { cpa_wait<0>(); }
        __syncthreads();
        int k0 = s << 4;
        int kt = IND - k0; if (kt > 16) kt = 16;
        const float* cA = sA[s & 1];
        const float* cW = sW[s & 1];
#define PRE2_BODY(k) do {                                                      \
            ulonglong2 a01 = *(const ulonglong2*)(cA + (k) * 64 + bg8);        \
            ulonglong2 a23 = *(const ulonglong2*)(cA + (k) * 64 + bg8 + 4);    \
            float4 w0 = *(const float4*)(cW + (k) * 256 + cg8);                \
            float4 w1 = *(const float4*)(cW + (k) * 256 + cg8 + 4);            \
            ull wp;                                                            \
            wp = pack2(w0.x, w0.x);                                            \
            fma2(acc[0][0], a01.x, wp); fma2(acc[0][1], a01.y, wp);            \
            fma2(acc[0][2], a23.x, wp); fma2(acc[0][3], a23.y, wp);            \
            wp = pack2(w0.y, w0.y);                                            \
            fma2(acc[1][0], a01.x, wp); fma2(acc[1][1], a01.y, wp);            \
            fma2(acc[1][2], a23.x, wp); fma2(acc[1][3], a23.y, wp);            \
            wp = pack2(w0.z, w0.z);                                            \
            fma2(acc[2][0], a01.x, wp); fma2(acc[2][1], a01.y, wp);            \
            fma2(acc[2][2], a23.x, wp); fma2(acc[2][3], a23.y, wp);            \
            wp = pack2(w0.w, w0.w);                                            \
            fma2(acc[3][0], a01.x, wp); fma2(acc[3][1], a01.y, wp);            \
            fma2(acc[3][2], a23.x, wp); fma2(acc[3][3], a23.y, wp);            \
            wp = pack2(w1.x, w1.x);                                            \
            fma2(acc[4][0], a01.x, wp); fma2(acc[4][1], a01.y, wp);            \
            fma2(acc[4][2], a23.x, wp); fma2(acc[4][3], a23.y, wp);            \
            wp = pack2(w1.y, w1.y);                                            \
            fma2(acc[5][0], a01.x, wp); fma2(acc[5][1], a01.y, wp);            \
            fma2(acc[5][2], a23.x, wp); fma2(acc[5][3], a23.y, wp);            \
            wp = pack2(w1.z, w1.z);                                            \
            fma2(acc[6][0], a01.x, wp); fma2(acc[6][1], a01.y, wp);            \
            fma2(acc[6][2], a23.x, wp); fma2(acc[6][3], a23.y, wp);            \
            wp = pack2(w1.w, w1.w);                                            \
            fma2(acc[7][0], a01.x, wp); fma2(acc[7][1], a01.y, wp);            \
            fma2(acc[7][2], a23.x, wp); fma2(acc[7][3], a23.y, wp);            \
        } while (0)
        if (kt == 16) {
#pragma unroll
            for (int k = 0; k < 16; k++) PRE2_BODY(k);
        } else {
            for (int k = 0; k < kt; k++) PRE2_BODY(k);
        }
#undef PRE2_BODY
        __syncthreads();
    }

    float* outT = (which == 0) ? &g_axp[t][0][0] : &g_gxh[t][0][0];
#pragma unroll
    for (int c = 0; c < 8; c++) {
        int col = cb + cg8 + c;
        ulonglong2 v0; v0.x = acc[c][0]; v0.y = acc[c][1];
        ulonglong2 v1; v1.x = acc[c][2]; v1.y = acc[c][3];
        *(ulonglong2*)(outT + col * 64 + bg8) = v0;
        *(ulonglong2*)(outT + col * 64 + bg8 + 4) = v1;
    }
}

// ---------------- THE persistent recurrence kernel (R9 proven) ---------------
__global__ void __launch_bounds__(256, 1) k_seq(
        const float* __restrict__ Wxh, const float* __restrict__ Whh,
        const float* __restrict__ bhy, const float* __restrict__ Wh,
        const float* __restrict__ Wzx, const float* __restrict__ bzx,
        const float* __restrict__ Wzh, const float* __restrict__ bzh,
        const float* __restrict__ Wzb, const float* __restrict__ b0,
        const float* __restrict__ Dx, const float* __restrict__ Dh,
        const float* __restrict__ Db) {
    // union: phase A/B use [0,6144) for mm32; phase C uses
    // sZ [0,6144), sWD [6144,7680), sPre [7680,11776)  -> 47KB
    __shared__ __align__(16) float sm[11776];
    const int bx = blockIdx.x;
    const int tid = threadIdx.x;
    const float* WxhH = Wxh + IND * 1024;

    const int cg4 = (tid >> 5) << 2;
    const int bg2 = (tid & 31) << 1;

    for (int t = 0; t < NSEQ; t++) {
        const int cur = t & 1, nxt = cur ^ 1;

        // ================= phase A: hyper (32 blocks) || h@Wh (116 blocks) ===
        if (bx < 32) {
            const int jbase = bx * 8;
            ull acc[4];
#pragma unroll
            for (int i = 0; i < 4; i++) {
                int c = cg4 + i;
                acc[i] = *(const ull*)(&g_gxh[t][((c >> 3) << 8) + jbase + (c & 7)][bg2]);
            }
            mm32<true>(&g_h[0][0],       WxhH, 1024, jbase, 32, sm, acc, tid);
            mm32<true>(&g_hh[cur][0][0], Whh,  1024, jbase, 8,  sm, acc, tid);

            float* sPre = sm;  // 2048 floats (free after mm32)
#pragma unroll
            for (int i = 0; i < 4; i++) {
                int c = cg4 + i;
                float bv = bhy[((c >> 3) << 8) + jbase + (c & 7)];
                *(ull*)(&sPre[c * 64 + bg2]) = add2(acc[i], pack2(bv, bv));
            }
            __syncthreads();
#pragma unroll
            for (int r = 0; r < 2; r++) {
                int idx = tid + (r << 8);
                int jl = idx >> 6, b = idx & 63;
                int jg = jbase + jl;
                float iv = sPre[jl * 64 + b];
                float fv = sPre[(8 + jl) * 64 + b];
                float gv = sPre[(16 + jl) * 64 + b];
                float ov = sPre[(24 + jl) * 64 + b];
                float chv = sigf(fv) * g_ch[jg][b] + sigf(iv) * tanhf(gv);
                g_ch[jg][b] = chv;
                g_hh[nxt][jg][b] = sigf(ov) * tanhf(chv);
            }
        } else {
            // h @ Wh : 512 units of (32 cols, K=256). 48 blocks x5, 68 blocks x4.
            int w0 = bx - 32;
            int start = (w0 < 48) ? w0 * 5 : 240 + (w0 - 48) * 4;
            int cnt = (w0 < 48) ? 5 : 4;
            for (int i = 0; i < cnt; i++) {
                int u = start + i;
                int ct = u >> 2, ks = u & 3;
                ull acc[4] = {};
                mm32<false>(&g_h[ks * 256][0], Wh + ks * 256 * 4096, 4096,
                            ct * 32, 8, sm, acc, tid);
#pragma unroll
                for (int c = 0; c < 4; c++)
                    *(ull*)(&g_ahp[ks][ct * 32 + cg4 + c][bg2]) = acc[c];
            }
        }
        grid_bar();

        // ================= phase B: z projections (24 blocks) ================
        if (bx < 24) {
            int type = bx >> 3, cb = (bx & 7) * 32;
            const float* W = (type == 0) ? Wzx : (type == 1) ? Wzh : Wzb;
            ull acc[4] = {};
            mm32<false>(&g_hh[nxt][0][0], W, 256, cb, 8, sm, acc, tid);
#pragma unroll
            for (int c = 0; c < 4; c++) {
                int col = cb + cg4 + c;
                float bv = (type == 0) ? bzx[col] : (type == 1) ? bzh[col] : 0.0f;
                *(ull*)(&g_z[type * 256 + col][bg2]) = add2(acc[c], pack2(bv, bv));
            }
        }
        grid_bar();

        // ================= phase C: einsums + combine + cell (64 blocks) =====
        if (bx < 64) {
            const int jt = bx;
            const int bg4 = (tid & 15) << 2;
            const int cg16 = tid >> 4;          // 0..15 -> 4 local cols
            const int gate = cg16 >> 2;
            const int j4 = (cg16 & 3) << 2;

            ull sx[4][2] = {}, sh[4][2] = {}, sb[4][2] = {};

            // stage loader: f-chunk of 4; sZ[ty][g][fr][64]  sWD[ty][fr][64]
            {
                int f0 = 0;
#pragma unroll
                for (int p = 0; p < 3; p++) {
                    int i = tid + (p << 8);
                    int b4 = (i & 15) << 2;
                    int r = i >> 4;
                    int fr = r & 3, g = (r >> 2) & 3, ty = r >> 4;
                    cpa16(sm + ((ty * 4 + g) * 4 + fr) * 64 + b4,
                          &g_z[ty * 256 + g * 64 + f0 + fr][b4]);
                }
                if (tid < 192) {
                    int ty = tid >> 6, rem = tid & 63;
                    int fr = rem >> 4, c4 = (rem & 15) << 2;
                    const float* D = (ty == 0) ? Dx : (ty == 1) ? Dh : Db;
                    cpa16(sm + 6144 + (ty * 4 + fr) * 64 + c4,
                          D + ((c4 >> 4) * 64 + f0 + fr) * 1024 + jt * 16 + (c4 & 15));
                }
                cpa_commit();
            }
            for (int st = 0; st < 16; st++) {
                int buf = st & 1;
                if (st + 1 < 16) {
                    int f0 = (st + 1) << 2;
                    float* dZ = sm + (buf ^ 1) * 3072;
                    float* dW = sm + 6144 + (buf ^ 1) * 768;
#pragma unroll
                    for (int p = 0; p < 3; p++) {
                        int i = tid + (p << 8);
                        int b4 = (i & 15) << 2;
                        int r = i >> 4;
                        int fr = r & 3, g = (r >> 2) & 3, ty = r >> 4;
                        cpa16(dZ + ((ty * 4 + g) * 4 + fr) * 64 + b4,
                              &g_z[ty * 256 + g * 64 + f0 + fr][b4]);
                    }
                    if (tid < 192) {
                        int ty = tid >> 6, rem = tid & 63;
                        int fr = rem >> 4, c4 = (rem & 15) << 2;
                        const float* D = (ty == 0) ? Dx : (ty == 1) ? Dh : Db;
                        cpa16(dW + (ty * 4 + fr) * 64 + c4,
                              D + ((c4 >> 4) * 64 + f0 + fr) * 1024 + jt * 16 + (c4 & 15));
                    }
                    cpa_commit();
                    cpa_wait<1>();
                } else {
                    cpa_wait<0>();
                }
                __syncthreads();
                const float* cZ = sm + buf * 3072;
                const float* cW = sm + 6144 + buf * 768;
#pragma unroll
                for (int k = 0; k < 4; k++) {
                    ulonglong2 azx = *(const ulonglong2*)(cZ + ((0 * 4 + gate) * 4 + k) * 64 + bg4);
                    ulonglong2 azh = *(const ulonglong2*)(cZ + ((1 * 4 + gate) * 4 + k) * 64 + bg4);
                    ulonglong2 azb = *(const ulonglong2*)(cZ + ((2 * 4 + gate) * 4 + k) * 64 + bg4);
                    float4 wx = *(const float4*)(cW + (0 * 4 + k) * 64 + cg16 * 4);
                    float4 wh = *(const float4*)(cW + (1 * 4 + k) * 64 + cg16 * 4);
                    float4 wb = *(const float4*)(cW + (2 * 4 + k) * 64 + cg16 * 4);
#pragma unroll
                    for (int c = 0; c < 4; c++) {
                        float wxc = (c == 0) ? wx.x : (c == 1) ? wx.y : (c == 2) ? wx.z : wx.w;
                        float whc = (c == 0) ? wh.x : (c == 1) ? wh.y : (c == 2) ? wh.z : wh.w;
                        float wbc = (c == 0) ? wb.x : (c == 1) ? wb.y : (c == 2) ? wb.z : wb.w;
                        ull wxp = pack2(wxc, wxc), whp = pack2(whc, whc), wbp = pack2(wbc, wbc);
                        fma2(sx[c][0], azx.x, wxp); fma2(sx[c][1], azx.y, wxp);
                        fma2(sh[c][0], azh.x, whp); fma2(sh[c][1], azh.y, whp);
                        fma2(sb[c][0], azb.x, wbp); fma2(sb[c][1], azb.y, wbp);
                    }
                }
                __syncthreads();
            }

            float* sPre = sm + 7680;  // 4096 floats: [64 cols][64 batch]
#pragma unroll
            for (int c = 0; c < 4; c++) {
                int jglob = jt * 16 + j4 + c;
                int col = gate * 1024 + jglob;
                ulonglong2 ax = *(const ulonglong2*)(&g_axp[t][col][bg4]);
                ulonglong2 a0 = *(const ulonglong2*)(&g_ahp[0][col][bg4]);
                ulonglong2 a1 = *(const ulonglong2*)(&g_ahp[1][col][bg4]);
                ulonglong2 a2 = *(const ulonglong2*)(&g_ahp[2][col][bg4]);
                ulonglong2 a3 = *(const ulonglong2*)(&g_ahp[3][col][bg4]);
                ull ahx = add2(add2(a0.x, a1.x), add2(a2.x, a3.x));
                ull ahy = add2(add2(a0.y, a1.y), add2(a2.y, a3.y));
                float bv = b0[gate * 1024 + jglob];
                ull bp = pack2(bv, bv);
                ull p0 = mul2(sx[c][0], ax.x); fma2(p0, sh[c][0], ahx);
                p0 = add2(p0, sb[c][0]); p0 = add2(p0, bp);
                ull p1 = mul2(sx[c][1], ax.y); fma2(p1, sh[c][1], ahy);
                p1 = add2(p1, sb[c][1]); p1 = add2(p1, bp);
                *(ull*)(&sPre[(gate * 16 + j4 + c) * 64 + bg4]) = p0;
                *(ull*)(&sPre[(gate * 16 + j4 + c) * 64 + bg4 + 2]) = p1;
            }
            __syncthreads();

#pragma unroll
            for (int r = 0; r < 4; r++) {
                int idx = tid + (r << 8);
                int jl = idx >> 6, b = idx & 63;
                int jg = jt * 16 + jl;
                float iv = sPre[(0 * 16 + jl) * 64 + b];
                float fv = sPre[(1 * 16 + jl) * 64 + b];
                float gv = sPre[(2 * 16 + jl) * 64 + b];
                float ov = sPre[(3 * 16 + jl) * 64 + b];
                float cv = sigf(fv) * g_c[jg][b] + sigf(iv) * tanhf(gv);
                g_c[jg][b] = cv;
                float hn = sigf(ov) * tanhf(cv);
                g_h[jg][b] = hn;
                g_outs[t][jg][b] = hn;
            }
        }
        grid_bar();
    }
}

// ---------------- epilogue ---------------------------------------------------
__global__ void __launch_bounds__(256) k_proj(const float* __restrict__ Wp,
                                              const float* __restrict__ bp) {
    __shared__ __align__(16) float smem[2048];
    float (*sA)[64] = (float(*)[64])smem;
    float (*sW)[64] = (float(*)[64])(smem + 1024);
    int t = blockIdx.y;
    int cb = blockIdx.x * 64;
    int tid = threadIdx.x;
    const float* A = &g_outs[t][0][0];
    const int row = tid >> 4;
    const int q4 = (tid & 15) << 2;
    const int bg4 = (tid & 15) << 2;
    const int cg4 = (tid >> 4) << 2;
    ull acc[4][2] = {};

    float4 pa = *(const float4*)(A + row * 64 + q4);
    float4 pw;
    {
        const float* wr = Wp + row * OUTD + cb + q4;
        pw.x = (cb + q4 + 0 < OUTD) ? wr[0] : 0.f;
        pw.y = (cb + q4 + 1 < OUTD) ? wr[1] : 0.f;
        pw.z = (cb + q4 + 2 < OUTD) ? wr[2] : 0.f;
        pw.w = (cb + q4 + 3 < OUTD) ? wr[3] : 0.f;
    }
    for (int s = 0; s < 64; s++) {
        __syncthreads();
        *(float4*)(&sA[row][q4]) = pa;
        *(float4*)(&sW[row][q4]) = pw;
        __syncthreads();
        if (s + 1 < 64) {
            int kn = (s + 1) * 16 + row;
            pa = *(const float4*)(A + kn * 64 + q4);
            const float* wr = Wp + kn * OUTD + cb + q4;
            pw.x = (cb + q4 + 0 < OUTD) ? wr[0] : 0.f;
            pw.y = (cb + q4 + 1 < OUTD) ? wr[1] : 0.f;
            pw.z = (cb + q4 + 2 < OUTD) ? wr[2] : 0.f;
            pw.w = (cb + q4 + 3 < OUTD) ? wr[3] : 0.f;
        }
#pragma unroll
        for (int k = 0; k < 16; k++) {
            ulonglong2 a = *(const ulonglong2*)(&sA[k][bg4]);
            float4 w = *(const float4*)(&sW[k][cg4]);
            ull w0 = pack2(w.x, w.x), w1 = pack2(w.y, w.y);
            ull w2 = pack2(w.z, w.z), w3 = pack2(w.w, w.w);
            fma2(acc[0][0], a.x, w0); fma2(acc[0][1], a.y, w0);
            fma2(acc[1][0], a.x, w1); fma2(acc[1][1], a.y, w1);
            fma2(acc[2][0], a.x, w2); fma2(acc[2][1], a.y, w2);
            fma2(acc[3][0], a.x, w3); fma2(acc[3][1], a.y, w3);
        }
    }
#pragma unroll
    for (int c = 0; c < 4; c++) {
        int col = cb + cg4 + c;
        if (col < OUTD) {
            float bv = bp[col];
            ull bpp = pack2(bv, bv);
            ulonglong2 v;
            v.x = add2(acc[c][0], bpp);
            v.y = add2(acc[c][1], bpp);
            *(ulonglong2*)(&g_dec[t][col][bg4]) = v;
        }
    }
}

__global__ void k_mdn(float* __restrict__ out) {
    int idx = blockIdx.x * blockDim.x + threadIdx.x;
    if (idx >= NSEQ * B * 21) return;
    int u = idx % 21;
    int r = idx / 21;
    int b = r & 63;
    int t = r >> 6;
    if (u < 20) {
        int m = u;
        int off = t * 20 * 64 + m * 64 + b;
        out[off] = 1.0f;
        out[163840 + off] = g_dec[t][6 * m + 1][b];
        out[327680 + off] = g_dec[t][6 * m + 2][b];
        out[491520 + off] = expf(g_dec[t][6 * m + 3][b]);
        out[655360 + off] = expf(g_dec[t][6 * m + 4][b]);
        out[819200 + off] = tanhf(g_dec[t][6 * m + 5][b]);
    } else {
        float p0 = g_dec[t][120][b], p1 = g_dec[t][121][b], p2 = g_dec[t][122][b];
        float mx = fmaxf(p0, fmaxf(p1, p2));
        float e0 = expf(p0 - mx), e1 = expf(p1 - mx), e2 = expf(p2 - mx);
        float s = e0 + e1 + e2;
        int base = 983040 + t * (B * 3) + b * 3;
        out[base + 0] = e0 / s;
        out[base + 1] = e1 / s;
        out[base + 2] = e2 / s;
    }
}

// ---------------- host driver ------------------------------------------------
extern "C" void kernel_launch(void* const* d_in, const int* in_sizes, int n_in,
                              void* d_out, int out_size) {
    const float* z        = (const float*)d_in[0];
    const float* strokes  = (const float*)d_in[1];
    const float* fc_in_w  = (const float*)d_in[2];
    const float* fc_in_b  = (const float*)d_in[3];
    const float* fc_proj_w= (const float*)d_in[4];
    const float* fc_proj_b= (const float*)d_in[5];
    const float* Wx       = (const float*)d_in[6];
    const float* Wh       = (const float*)d_in[7];
    const float* b0       = (const float*)d_in[8];
    const float* Wxh      = (const float*)d_in[9];
    const float* Whh      = (const float*)d_in[10];
    const float* bhy      = (const float*)d_in[11];
    const float* Wzx      = (const float*)d_in[12];
    const float* bzx      = (const float*)d_in[13];
    const float* Wzh      = (const float*)d_in[14];
    const float* bzh      = (const float*)d_in[15];
    const float* Wzb      = (const float*)d_in[16];
    const float* Dx       = (const float*)d_in[17];
    const float* Dh       = (const float*)d_in[18];
    const float* Db       = (const float*)d_in[19];
    float* out = (float*)d_out;

    k_transpose<<<(NSEQ * B * IND + 255) / 256, 256>>>(strokes);
    k_init<<<(B * 2560 + 255) / 256, 256>>>(z, fc_in_w, fc_in_b);
    // x @ Wx : 4096 cols -> 16 ctiles ; x @ Wxh(x-rows) : 1024 cols -> 4 ctiles
    k_pre2<<<dim3(16, NSEQ), 256>>>(Wx, 4096, 0);
    k_pre2<<<dim3(4, NSEQ), 256>>>(Wxh, 1024, 1);

    k_seq<<<GRID, 256>>>(Wxh, Whh, bhy, Wh, Wzx, bzx, Wzh, bzh, Wzb,
                         b0, Dx, Dh, Db);

    dim3 pg(2, NSEQ);
    k_proj<<<pg, 256>>>(fc_proj_w, fc_proj_b);
    k_mdn<<<(NSEQ * B * 21 + 255) / 256, 256>>>(out);
}

// round 17
// speedup vs baseline: 1.2967x; 1.0976x over previous
#include <cuda_runtime.h>
#include <math.h>
#include <stdint.h>

typedef unsigned long long ull;

#define B 64
#define H 1024
#define HY 256
#define F 64
#define IND 133
#define NSEQ 128
#define OUTD 123
#define GRID 148

// ---------------- persistent device state ----------------------------------
__device__ __align__(16) float g_h[H][B];
__device__ __align__(16) float g_c[H][B];
__device__ __align__(16) float g_hh[2][HY][B];
__device__ __align__(16) float g_ch[HY][B];
__device__ __align__(16) float g_ahp[4][4 * H][B];      // h@Wh split-K partials
__device__ __align__(16) float g_x[NSEQ][IND][B];
__device__ __align__(16) float g_axp[NSEQ][4 * H][B];   // precomputed x@Wx
__device__ __align__(16) float g_gxh[NSEQ][4 * HY][B];  // precomputed x@Wxh(x-rows)
__device__ __align__(16) float g_E[3][HY][4 * H];       // fused Wz@D (12.6MB)
__device__ __align__(16) float g_Ebias[2][4 * H];       // bz@D (zb has no bias)
__device__ __align__(16) float g_outs[NSEQ][H][B];
__device__ __align__(16) float g_dec[NSEQ][OUTD][B];
__device__ unsigned g_bar_count;
__device__ unsigned g_bar_gen;

__device__ __forceinline__ float sigf(float x) { return 1.0f / (1.0f + expf(-x)); }

__device__ __forceinline__ void fma2(ull& d, ull a, ull b) {
    asm("fma.rn.f32x2 %0, %1, %2, %0;" : "+l"(d) : "l"(a), "l"(b));
}
__device__ __forceinline__ ull mul2(ull a, ull b) {
    ull d; asm("mul.rn.f32x2 %0, %1, %2;" : "=l"(d) : "l"(a), "l"(b)); return d;
}
__device__ __forceinline__ ull add2(ull a, ull b) {
    ull d; asm("add.rn.f32x2 %0, %1, %2;" : "=l"(d) : "l"(a), "l"(b)); return d;
}
__device__ __forceinline__ ull pack2(float x, float y) {
    ull r; asm("mov.b64 %0, {%1, %2};" : "=l"(r) : "f"(x), "f"(y)); return r;
}

// ---------------- cp.async helpers ------------------------------------------
__device__ __forceinline__ void cpa16(void* dst, const void* src) {
    unsigned d = (unsigned)__cvta_generic_to_shared(dst);
    asm volatile("cp.async.cg.shared.global [%0], [%1], 16;" :: "r"(d), "l"(src));
}
__device__ __forceinline__ void cpa_commit() {
    asm volatile("cp.async.commit_group;");
}
template<int N>
__device__ __forceinline__ void cpa_wait() {
    asm volatile("cp.async.wait_group %0;" :: "n"(N));
}

// ---------------- grid-wide barrier (R9 proven version) ----------------------
__device__ __forceinline__ void grid_bar() {
    __syncthreads();
    if (threadIdx.x == 0) {
        unsigned gen = *(volatile unsigned*)&g_bar_gen;
        __threadfence();
        unsigned arr = atomicAdd(&g_bar_count, 1u);
        if (arr == GRID - 1) {
            *(volatile unsigned*)&g_bar_count = 0u;
            __threadfence();
            *(volatile unsigned*)&g_bar_gen = gen + 1u;
        } else {
            while (*(volatile unsigned*)&g_bar_gen == gen) {}
        }
        __threadfence();
    }
    __syncthreads();
}

// ---------------- double-buffered 32-col GEMM core (R9 proven) ---------------
// acc[4] (+=): cols cb..cb+31 (thread: cols cg4..cg4+3 where cg4=(tid>>5)<<2,
// batch pair bg2=(tid&31)<<1), K = 32*nst over A[k][64].
// GATHER: W cols are 4 gate-strided groups of 8 at stride 256 (cb = jbase).
// smem: sA = sm[0..4096), sW = sm[4096..6144).
template<bool GATHER>
__device__ __forceinline__ void mm32(const float* __restrict__ A,
                                     const float* __restrict__ W,
                                     int ldw, int cb, int nst,
                                     float* sm, ull (&acc)[4], int tid) {
    float* sA = sm;
    float* sW = sm + 4096;
    const int ar  = tid >> 4;
    const int ac4 = (tid & 15) << 2;
    const int wr  = tid >> 3;
    const int wq  = tid & 7;
    const int cg4 = (tid >> 5) << 2;
    const int bg2 = (tid & 31) << 1;

    {
        cpa16(sA + ar * 64 + ac4, A + ar * 64 + ac4);
        cpa16(sA + (ar + 16) * 64 + ac4, A + (ar + 16) * 64 + ac4);
        const float* ws = GATHER
            ? (W + wr * ldw + ((wq >> 1) << 8) + cb + ((wq & 1) << 2))
            : (W + wr * ldw + cb + (wq << 2));
        cpa16(sW + wr * 32 + (wq << 2), ws);
        cpa_commit();
    }
    for (int s = 0; s < nst; s++) {
        int buf = s & 1;
        if (s + 1 < nst) {
            int k0 = (s + 1) << 5;
            float* dA = sA + (buf ^ 1) * 2048;
            float* dW = sW + (buf ^ 1) * 1024;
            cpa16(dA + ar * 64 + ac4, A + (k0 + ar) * 64 + ac4);
            cpa16(dA + (ar + 16) * 64 + ac4, A + (k0 + ar + 16) * 64 + ac4);
            const float* ws = GATHER
                ? (W + (k0 + wr) * ldw + ((wq >> 1) << 8) + cb + ((wq & 1) << 2))
                : (W + (k0 + wr) * ldw + cb + (wq << 2));
            cpa16(dW + wr * 32 + (wq << 2), ws);
            cpa_commit();
            cpa_wait<1>();
        } else {
            cpa_wait<0>();
        }
        __syncthreads();
        const float* cA = sA + buf * 2048;
        const float* cW = sW + buf * 1024;
#pragma unroll
        for (int k = 0; k < 32; k++) {
            ull a = *(const ull*)(cA + k * 64 + bg2);
            float4 w = *(const float4*)(cW + k * 32 + cg4);
            fma2(acc[0], a, pack2(w.x, w.x));
            fma2(acc[1], a, pack2(w.y, w.y));
            fma2(acc[2], a, pack2(w.z, w.z));
            fma2(acc[3], a, pack2(w.w, w.w));
        }
        __syncthreads();
    }
}

// ---------------- prologue kernels ------------------------------------------
__global__ void k_transpose(const float* __restrict__ strokes) {
    int idx = blockIdx.x * blockDim.x + threadIdx.x;
    if (idx >= NSEQ * B * IND) return;
    int t = idx / (B * IND);
    int r = idx - t * (B * IND);
    int b = r / IND;
    int k = r - b * IND;
    g_x[t][k][b] = strokes[idx];
}

__global__ void k_init(const float* __restrict__ z, const float* __restrict__ w,
                       const float* __restrict__ bias) {
    int idx = blockIdx.x * blockDim.x + threadIdx.x;
    int b = idx & 63;
    int col = idx >> 6;
    if (col >= 2560) return;
    float acc = bias[col];
#pragma unroll 4
    for (int k = 0; k < 128; k++) acc += z[b * 128 + k] * w[k * 2560 + col];
    float v = tanhf(acc);
    if (col < 1024)       g_h[col][b] = v;
    else if (col < 2048)  g_c[col - 1024][b] = v;
    else if (col < 2304)  g_hh[0][col - 2048][b] = v;
    else                  g_ch[col - 2304][b] = v;
}

// Big-tile x-projection (R16 proven): 256 cols x 64 batch per block.
__global__ void __launch_bounds__(256, 2) k_pre2(const float* __restrict__ W,
                                                 int ldw, int which) {
    __shared__ __align__(16) float sA[2][1024];
    __shared__ __align__(16) float sW[2][4096];
    const int t = blockIdx.y;
    const int cb = blockIdx.x * 256;
    const int tid = threadIdx.x;
    const float* A = &g_x[t][0][0];
    const int bg8 = (tid & 7) << 3;
    const int cg8 = (tid >> 3) << 3;
    const int NST = (IND + 15) >> 4;  // 9

    auto load = [&](int s) {
        int k0 = s << 4;
        int kt = IND - k0; if (kt > 16) kt = 16;
        int buf = s & 1;
        {
            int row = tid >> 4, b4 = (tid & 15) << 2;
            if (row < kt) cpa16(&sA[buf][row * 64 + b4], A + (k0 + row) * 64 + b4);
        }
#pragma unroll
        for (int p = 0; p < 4; p++) {
            int i = tid + (p << 8);
            int row = i >> 6, c4 = (i & 63) << 2;
            if (row < kt) cpa16(&sW[buf][row * 256 + c4], W + (k0 + row) * ldw + cb + c4);
        }
        cpa_commit();
    };

    load(0);
    ull acc[8][4] = {};
    for (int s = 0; s < NST; s++) {
        if (s + 1 < NST) { load(s + 1); cpa_wait<1>(); } else { cpa_wait<0>(); }
        __syncthreads();
        int k0 = s << 4;
        int kt = IND - k0; if (kt > 16) kt = 16;
        const float* cA = sA[s & 1];
        const float* cW = sW[s & 1];
#define PRE2_BODY(k) do {                                                      \
            ulonglong2 a01 = *(const ulonglong2*)(cA + (k) * 64 + bg8);        \
            ulonglong2 a23 = *(const ulonglong2*)(cA + (k) * 64 + bg8 + 4);    \
            float4 w0 = *(const float4*)(cW + (k) * 256 + cg8);                \
            float4 w1 = *(const float4*)(cW + (k) * 256 + cg8 + 4);            \
            ull wp;                                                            \
            wp = pack2(w0.x, w0.x);                                            \
            fma2(acc[0][0], a01.x, wp); fma2(acc[0][1], a01.y, wp);            \
            fma2(acc[0][2], a23.x, wp); fma2(acc[0][3], a23.y, wp);            \
            wp = pack2(w0.y, w0.y);                                            \
            fma2(acc[1][0], a01.x, wp); fma2(acc[1][1], a01.y, wp);            \
            fma2(acc[1][2], a23.x, wp); fma2(acc[1][3], a23.y, wp);            \
            wp = pack2(w0.z, w0.z);                                            \
            fma2(acc[2][0], a01.x, wp); fma2(acc[2][1], a01.y, wp);            \
            fma2(acc[2][2], a23.x, wp); fma2(acc[2][3], a23.y, wp);            \
            wp = pack2(w0.w, w0.w);                                            \
            fma2(acc[3][0], a01.x, wp); fma2(acc[3][1], a01.y, wp);            \
            fma2(acc[3][2], a23.x, wp); fma2(acc[3][3], a23.y, wp);            \
            wp = pack2(w1.x, w1.x);                                            \
            fma2(acc[4][0], a01.x, wp); fma2(acc[4][1], a01.y, wp);            \
            fma2(acc[4][2], a23.x, wp); fma2(acc[4][3], a23.y, wp);            \
            wp = pack2(w1.y, w1.y);                                            \
            fma2(acc[5][0], a01.x, wp); fma2(acc[5][1], a01.y, wp);            \
            fma2(acc[5][2], a23.x, wp); fma2(acc[5][3], a23.y, wp);            \
            wp = pack2(w1.z, w1.z);                                            \
            fma2(acc[6][0], a01.x, wp); fma2(acc[6][1], a01.y, wp);            \
            fma2(acc[6][2], a23.x, wp); fma2(acc[6][3], a23.y, wp);            \
            wp = pack2(w1.w, w1.w);                                            \
            fma2(acc[7][0], a01.x, wp); fma2(acc[7][1], a01.y, wp);            \
            fma2(acc[7][2], a23.x, wp); fma2(acc[7][3], a23.y, wp);            \
        } while (0)
        if (kt == 16) {
#pragma unroll
            for (int k = 0; k < 16; k++) PRE2_BODY(k);
        } else {
            for (int k = 0; k < kt; k++) PRE2_BODY(k);
        }
#undef PRE2_BODY
        __syncthreads();
    }

    float* outT = (which == 0) ? &g_axp[t][0][0] : &g_gxh[t][0][0];
#pragma unroll
    for (int c = 0; c < 8; c++) {
        int col = cb + cg8 + c;
        ulonglong2 v0; v0.x = acc[c][0]; v0.y = acc[c][1];
        ulonglong2 v1; v1.x = acc[c][2]; v1.y = acc[c][3];
        *(ulonglong2*)(outT + col * 64 + bg8) = v0;
        *(ulonglong2*)(outT + col * 64 + bg8 + 4) = v1;
    }
}

// E[ty][k][g*1024+j] = sum_f Wz[ty][k][g*64+f] * D[ty][g][f][j]  (R10 proven)
__global__ void __launch_bounds__(256) k_pre_E(
        const float* __restrict__ Wzx, const float* __restrict__ Wzh,
        const float* __restrict__ Wzb,
        const float* __restrict__ Dx, const float* __restrict__ Dh,
        const float* __restrict__ Db) {
    int ty = blockIdx.z, k = blockIdx.y;
    int g = blockIdx.x >> 2, jc = (blockIdx.x & 3) << 8;
    const float* Wz = (ty == 0) ? Wzx : (ty == 1) ? Wzh : Wzb;
    const float* D  = (ty == 0) ? Dx  : (ty == 1) ? Dh  : Db;
    __shared__ float sw[64];
    if (threadIdx.x < 64) sw[threadIdx.x] = Wz[k * 256 + g * 64 + threadIdx.x];
    __syncthreads();
    int j = jc + threadIdx.x;
    float acc = 0.f;
#pragma unroll 16
    for (int f = 0; f < 64; f++) acc += sw[f] * D[(g * 64 + f) * 1024 + j];
    g_E[ty][k][g * 1024 + j] = acc;
}

// Ebias[ty][g*1024+j] = sum_f bz[ty][g*64+f] * D[ty][g][f][j]  (R10 proven)
__global__ void k_pre_Eb(const float* __restrict__ bzx, const float* __restrict__ bzh,
                         const float* __restrict__ Dx, const float* __restrict__ Dh) {
    int idx = blockIdx.x * 256 + threadIdx.x;
    if (idx >= 8192) return;
    int ty = idx >> 12, col = idx & 4095;
    int g = col >> 10, j = col & 1023;
    const float* bb = ty ? bzh : bzx;
    const float* D  = ty ? Dh  : Dx;
    float acc = 0.f;
#pragma unroll 16
    for (int f = 0; f < 64; f++) acc += bb[g * 64 + f] * D[(g * 64 + f) * 1024 + j];
    g_Ebias[ty][col] = acc;
}

// ---------------- THE persistent recurrence kernel (2 phases/step) ----------
__global__ void __launch_bounds__(256, 1) k_seq(
        const float* __restrict__ Wxh, const float* __restrict__ Whh,
        const float* __restrict__ bhy, const float* __restrict__ Wh,
        const float* __restrict__ b0) {
    // smem: phase A mm32 uses [0,6144); P2: sA [0,4096) x2buf, sW [4096,10240)
    // x2buf(3x1024 each); sPre overlays [0,2048) after drains.  40KB total.
    __shared__ __align__(16) float sm[10240];
    const int bx = blockIdx.x;
    const int tid = threadIdx.x;
    const float* WxhH = Wxh + IND * 1024;

    const int cg4 = (tid >> 5) << 2;
    const int bg2 = (tid & 31) << 1;

    for (int t = 0; t < NSEQ; t++) {
        const int cur = t & 1, nxt = cur ^ 1;

        // ===== phase A: hyper (32 blocks) || h@Wh (116 blocks) ===============
        if (bx < 32) {
            const int jbase = bx * 8;
            ull acc[4];
#pragma unroll
            for (int i = 0; i < 4; i++) {
                int c = cg4 + i;
                acc[i] = *(const ull*)(&g_gxh[t][((c >> 3) << 8) + jbase + (c & 7)][bg2]);
            }
            mm32<true>(&g_h[0][0],       WxhH, 1024, jbase, 32, sm, acc, tid);
            mm32<true>(&g_hh[cur][0][0], Whh,  1024, jbase, 8,  sm, acc, tid);

            float* sPre = sm;  // free after mm32 drains
#pragma unroll
            for (int i = 0; i < 4; i++) {
                int c = cg4 + i;
                float bv = bhy[((c >> 3) << 8) + jbase + (c & 7)];
                *(ull*)(&sPre[c * 64 + bg2]) = add2(acc[i], pack2(bv, bv));
            }
            __syncthreads();
#pragma unroll
            for (int r = 0; r < 2; r++) {
                int idx = tid + (r << 8);
                int jl = idx >> 6, b = idx & 63;
                int jg = jbase + jl;
                float iv = sPre[jl * 64 + b];
                float fv = sPre[(8 + jl) * 64 + b];
                float gv = sPre[(16 + jl) * 64 + b];
                float ov = sPre[(24 + jl) * 64 + b];
                float chv = sigf(fv) * g_ch[jg][b] + sigf(iv) * tanhf(gv);
                g_ch[jg][b] = chv;
                g_hh[nxt][jg][b] = sigf(ov) * tanhf(chv);
            }
        } else {
            // h @ Wh : 512 units of (32 cols, K=256). 48 blocks x5, 68 blocks x4.
            int w0 = bx - 32;
            int start = (w0 < 48) ? w0 * 5 : 240 + (w0 - 48) * 4;
            int cnt = (w0 < 48) ? 5 : 4;
            for (int i = 0; i < cnt; i++) {
                int u = start + i;
                int ct = u >> 2, ks = u & 3;
                ull acc[4] = {};
                mm32<false>(&g_h[ks * 256][0], Wh + ks * 256 * 4096, 4096,
                            ct * 32, 8, sm, acc, tid);
#pragma unroll
                for (int c = 0; c < 4; c++)
                    *(ull*)(&g_ahp[ks][ct * 32 + cg4 + c][bg2]) = acc[c];
            }
        }
        grid_bar();

        // ===== P2: fused sx/sh/sb = hh@E (+Eb), combine, cell (128 blocks) ===
        if (bx < 128) {
            const int jb8 = bx * 8;
            const float* A  = &g_hh[nxt][0][0];
            const float* E0 = &g_E[0][0][0];
            const float* E1 = &g_E[1][0][0];
            const float* E2 = &g_E[2][0][0];
            float* sA = sm;
            float* sW = sm + 4096;
            const int ar  = tid >> 4;
            const int ac4 = (tid & 15) << 2;
            const int wr  = tid >> 3;
            const int wq  = tid & 7;

            ull sx[4] = {}, sh[4] = {}, sb[4] = {};

            // stage 0
            {
                cpa16(sA + ar * 64 + ac4, A + ar * 64 + ac4);
                cpa16(sA + (ar + 16) * 64 + ac4, A + (ar + 16) * 64 + ac4);
                int wcol = ((wq >> 1) << 10) + jb8 + ((wq & 1) << 2);
                cpa16(sW + wr * 32 + (wq << 2),          E0 + wr * 4096 + wcol);
                cpa16(sW + 1024 + wr * 32 + (wq << 2),   E1 + wr * 4096 + wcol);
                cpa16(sW + 2048 + wr * 32 + (wq << 2),   E2 + wr * 4096 + wcol);
                cpa_commit();
            }
            for (int s = 0; s < 8; s++) {
                int buf = s & 1;
                if (s + 1 < 8) {
                    int k0 = (s + 1) << 5;
                    float* dA = sA + (buf ^ 1) * 2048;
                    float* dW = sW + (buf ^ 1) * 3072;
                    cpa16(dA + ar * 64 + ac4, A + (k0 + ar) * 64 + ac4);
                    cpa16(dA + (ar + 16) * 64 + ac4, A + (k0 + ar + 16) * 64 + ac4);
                    int wcol = ((wq >> 1) << 10) + jb8 + ((wq & 1) << 2);
                    cpa16(dW + wr * 32 + (wq << 2),        E0 + (k0 + wr) * 4096 + wcol);
                    cpa16(dW + 1024 + wr * 32 + (wq << 2), E1 + (k0 + wr) * 4096 + wcol);
                    cpa16(dW + 2048 + wr * 32 + (wq << 2), E2 + (k0 + wr) * 4096 + wcol);
                    cpa_commit();
                    cpa_wait<1>();
                } else {
                    cpa_wait<0>();
                }
                __syncthreads();
                const float* cA = sA + buf * 2048;
                const float* cW = sW + buf * 3072;
#pragma unroll
                for (int k = 0; k < 32; k++) {
                    ull a = *(const ull*)(cA + k * 64 + bg2);
                    float4 wx = *(const float4*)(cW + k * 32 + cg4);
                    float4 wh = *(const float4*)(cW + 1024 + k * 32 + cg4);
                    float4 wb = *(const float4*)(cW + 2048 + k * 32 + cg4);
                    fma2(sx[0], a, pack2(wx.x, wx.x));
                    fma2(sx[1], a, pack2(wx.y, wx.y));
                    fma2(sx[2], a, pack2(wx.z, wx.z));
                    fma2(sx[3], a, pack2(wx.w, wx.w));
                    fma2(sh[0], a, pack2(wh.x, wh.x));
                    fma2(sh[1], a, pack2(wh.y, wh.y));
                    fma2(sh[2], a, pack2(wh.z, wh.z));
                    fma2(sh[3], a, pack2(wh.w, wh.w));
                    fma2(sb[0], a, pack2(wb.x, wb.x));
                    fma2(sb[1], a, pack2(wb.y, wb.y));
                    fma2(sb[2], a, pack2(wb.z, wb.z));
                    fma2(sb[3], a, pack2(wb.w, wb.w));
                }
                __syncthreads();
            }

            // combine + main cell (R10 proven tail)
            float* sPre = sm;  // overlays buf0 (pipeline drained; last reads buf1)
#pragma unroll
            for (int i = 0; i < 4; i++) {
                int c = cg4 + i;                  // local col: g*8 + jl
                int g = c >> 3, jl = c & 7;
                int col = (g << 10) + jb8 + jl;
                ull ax = *(const ull*)(&g_axp[t][col][bg2]);
                ull h0 = *(const ull*)(&g_ahp[0][col][bg2]);
                ull h1 = *(const ull*)(&g_ahp[1][col][bg2]);
                ull h2 = *(const ull*)(&g_ahp[2][col][bg2]);
                ull h3 = *(const ull*)(&g_ahp[3][col][bg2]);
                ull ah = add2(add2(h0, h1), add2(h2, h3));
                float ebx = g_Ebias[0][col];
                float ebh = g_Ebias[1][col];
                float b0v = b0[col];
                ull sxv = add2(sx[i], pack2(ebx, ebx));
                ull shv = add2(sh[i], pack2(ebh, ebh));
                ull p = mul2(sxv, ax);
                fma2(p, shv, ah);
                p = add2(p, sb[i]);
                p = add2(p, pack2(b0v, b0v));
                *(ull*)(&sPre[c * 64 + bg2]) = p;
            }
            __syncthreads();

#pragma unroll
            for (int r = 0; r < 2; r++) {
                int idx = tid + (r << 8);
                int jl = idx >> 6, b = idx & 63;
                int jg = jb8 + jl;
                float iv = sPre[(0 * 8 + jl) * 64 + b];
                float fv = sPre[(1 * 8 + jl) * 64 + b];
                float gv = sPre[(2 * 8 + jl) * 64 + b];
                float ov = sPre[(3 * 8 + jl) * 64 + b];
                float cv = sigf(fv) * g_c[jg][b] + sigf(iv) * tanhf(gv);
                g_c[jg][b] = cv;
                float hn = sigf(ov) * tanhf(cv);
                g_h[jg][b] = hn;
                g_outs[t][jg][b] = hn;
            }
        }
        grid_bar();
    }
}

// ---------------- epilogue ---------------------------------------------------
__global__ void __launch_bounds__(256) k_proj(const float* __restrict__ Wp,
                                              const float* __restrict__ bp) {
    __shared__ __align__(16) float smem[2048];
    float (*sA)[64] = (float(*)[64])smem;
    float (*sW)[64] = (float(*)[64])(smem + 1024);
    int t = blockIdx.y;
    int cb = blockIdx.x * 64;
    int tid = threadIdx.x;
    const float* A = &g_outs[t][0][0];
    const int row = tid >> 4;
    const int q4 = (tid & 15) << 2;
    const int bg4 = (tid & 15) << 2;
    const int cg4 = (tid >> 4) << 2;
    ull acc[4][2] = {};

    float4 pa = *(const float4*)(A + row * 64 + q4);
    float4 pw;
    {
        const float* wr = Wp + row * OUTD + cb + q4;
        pw.x = (cb + q4 + 0 < OUTD) ? wr[0] : 0.f;
        pw.y = (cb + q4 + 1 < OUTD) ? wr[1] : 0.f;
        pw.z = (cb + q4 + 2 < OUTD) ? wr[2] : 0.f;
        pw.w = (cb + q4 + 3 < OUTD) ? wr[3] : 0.f;
    }
    for (int s = 0; s < 64; s++) {
        __syncthreads();
        *(float4*)(&sA[row][q4]) = pa;
        *(float4*)(&sW[row][q4]) = pw;
        __syncthreads();
        if (s + 1 < 64) {
            int kn = (s + 1) * 16 + row;
            pa = *(const float4*)(A + kn * 64 + q4);
            const float* wr = Wp + kn * OUTD + cb + q4;
            pw.x = (cb + q4 + 0 < OUTD) ? wr[0] : 0.f;
            pw.y = (cb + q4 + 1 < OUTD) ? wr[1] : 0.f;
            pw.z = (cb + q4 + 2 < OUTD) ? wr[2] : 0.f;
            pw.w = (cb + q4 + 3 < OUTD) ? wr[3] : 0.f;
        }
#pragma unroll
        for (int k = 0; k < 16; k++) {
            ulonglong2 a = *(const ulonglong2*)(&sA[k][bg4]);
            float4 w = *(const float4*)(&sW[k][cg4]);
            ull w0 = pack2(w.x, w.x), w1 = pack2(w.y, w.y);
            ull w2 = pack2(w.z, w.z), w3 = pack2(w.w, w.w);
            fma2(acc[0][0], a.x, w0); fma2(acc[0][1], a.y, w0);
            fma2(acc[1][0], a.x, w1); fma2(acc[1][1], a.y, w1);
            fma2(acc[2][0], a.x, w2); fma2(acc[2][1], a.y, w2);
            fma2(acc[3][0], a.x, w3); fma2(acc[3][1], a.y, w3);
        }
    }
#pragma unroll
    for (int c = 0; c < 4; c++) {
        int col = cb + cg4 + c;
        if (col < OUTD) {
            float bv = bp[col];
            ull bpp = pack2(bv, bv);
            ulonglong2 v;
            v.x = add2(acc[c][0], bpp);
            v.y = add2(acc[c][1], bpp);
            *(ulonglong2*)(&g_dec[t][col][bg4]) = v;
        }
    }
}

__global__ void k_mdn(float* __restrict__ out) {
    int idx = blockIdx.x * blockDim.x + threadIdx.x;
    if (idx >= NSEQ * B * 21) return;
    int u = idx % 21;
    int r = idx / 21;
    int b = r & 63;
    int t = r >> 6;
    if (u < 20) {
        int m = u;
        int off = t * 20 * 64 + m * 64 + b;
        out[off] = 1.0f;
        out[163840 + off] = g_dec[t][6 * m + 1][b];
        out[327680 + off] = g_dec[t][6 * m + 2][b];
        out[491520 + off] = expf(g_dec[t][6 * m + 3][b]);
        out[655360 + off] = expf(g_dec[t][6 * m + 4][b]);
        out[819200 + off] = tanhf(g_dec[t][6 * m + 5][b]);
    } else {
        float p0 = g_dec[t][120][b], p1 = g_dec[t][121][b], p2 = g_dec[t][122][b];
        float mx = fmaxf(p0, fmaxf(p1, p2));
        float e0 = expf(p0 - mx), e1 = expf(p1 - mx), e2 = expf(p2 - mx);
        float s = e0 + e1 + e2;
        int base = 983040 + t * (B * 3) + b * 3;
        out[base + 0] = e0 / s;
        out[base + 1] = e1 / s;
        out[base + 2] = e2 / s;
    }
}

// ---------------- host driver ------------------------------------------------
extern "C" void kernel_launch(void* const* d_in, const int* in_sizes, int n_in,
                              void* d_out, int out_size) {
    const float* z        = (const float*)d_in[0];
    const float* strokes  = (const float*)d_in[1];
    const float* fc_in_w  = (const float*)d_in[2];
    const float* fc_in_b  = (const float*)d_in[3];
    const float* fc_proj_w= (const float*)d_in[4];
    const float* fc_proj_b= (const float*)d_in[5];
    const float* Wx       = (const float*)d_in[6];
    const float* Wh       = (const float*)d_in[7];
    const float* b0       = (const float*)d_in[8];
    const float* Wxh      = (const float*)d_in[9];
    const float* Whh      = (const float*)d_in[10];
    const float* bhy      = (const float*)d_in[11];
    const float* Wzx      = (const float*)d_in[12];
    const float* bzx      = (const float*)d_in[13];
    const float* Wzh      = (const float*)d_in[14];
    const float* bzh      = (const float*)d_in[15];
    const float* Wzb      = (const float*)d_in[16];
    const float* Dx       = (const float*)d_in[17];
    const float* Dh       = (const float*)d_in[18];
    const float* Db       = (const float*)d_in[19];
    float* out = (float*)d_out;

    k_transpose<<<(NSEQ * B * IND + 255) / 256, 256>>>(strokes);
    k_init<<<(B * 2560 + 255) / 256, 256>>>(z, fc_in_w, fc_in_b);
    k_pre2<<<dim3(16, NSEQ), 256>>>(Wx, 4096, 0);
    k_pre2<<<dim3(4, NSEQ), 256>>>(Wxh, 1024, 1);
    k_pre_E<<<dim3(16, HY, 3), 256>>>(Wzx, Wzh, Wzb, Dx, Dh, Db);
    k_pre_Eb<<<32, 256>>>(bzx, bzh, Dx, Dh);

    k_seq<<<GRID, 256>>>(Wxh, Whh, bhy, Wh, b0);

    dim3 pg(2, NSEQ);
    k_proj<<<pg, 256>>>(fc_proj_w, fc_proj_b);
    k_mdn<<<(NSEQ * B * 21 + 255) / 256, 256>>>(out);
}